// round 5
// baseline (speedup 1.0000x reference)
#include <cuda_runtime.h>
#include <math.h>

#define BATCH 4
#define CDIM  64
#define HH    256
#define WW    256
#define HWD   65536          // H*W
#define CHROWS 16384         // C*H
#define HID   170
#define HID2  340

// ---------------- scratch (device globals; no allocations allowed) ----------------
__device__ float g_bufA[(size_t)BATCH * CDIM * HWD];
__device__ float g_bufM[(size_t)BATCH * CDIM * HWD];
__device__ float g_bufZ[(size_t)BATCH * CDIM * HWD];
__device__ float g_qkv1[(size_t)BATCH * HID2 * HWD];
__device__ float g_qkv2[(size_t)BATCH * HID2 * HWD];
__device__ float g_attn[(size_t)BATCH * WW * WW];
__device__ float g_sq[BATCH * HH];
__device__ float g_sk[BATCH * HH];
__device__ float g_wpad[64 * 176];

// ---------------- helpers ----------------
__device__ __forceinline__ void mma8(float* d, unsigned a0, unsigned a1, unsigned a2, unsigned a3,
                                     unsigned b0, unsigned b1) {
    asm volatile(
        "mma.sync.aligned.m16n8k8.row.col.f32.tf32.tf32.f32 "
        "{%0,%1,%2,%3},{%4,%5,%6,%7},{%8,%9},{%0,%1,%2,%3};\n"
        : "+f"(d[0]), "+f"(d[1]), "+f"(d[2]), "+f"(d[3])
        : "r"(a0), "r"(a1), "r"(a2), "r"(a3), "r"(b0), "r"(b1));
}
#define CPA16(dst_u32, src_ptr) \
    asm volatile("cp.async.cg.shared.global [%0], [%1], 16;" :: "r"(dst_u32), "l"(src_ptr))

// ---------------- LayerNorm over channel dim (per pixel) ----------------
__global__ void ln_kernel(const float* __restrict__ x, const float* __restrict__ w,
                          const float* __restrict__ b, float* __restrict__ y)
{
    long p = (long)blockIdx.x * blockDim.x + threadIdx.x;
    if (p >= (long)BATCH * HWD) return;
    int bb  = (int)(p >> 16);
    int pix = (int)(p & (HWD - 1));
    const float* xp = x + (long)bb * CDIM * HWD + pix;
    float s = 0.f, s2 = 0.f;
#pragma unroll
    for (int c = 0; c < CDIM; c++) {
        float v = xp[(long)c * HWD];
        s += v; s2 += v * v;
    }
    float mu  = s * (1.0f / CDIM);
    float var = s2 * (1.0f / CDIM) - mu * mu;
    float inv = rsqrtf(var + 1e-5f);
    float* yp = y + (long)bb * CDIM * HWD + pix;
#pragma unroll
    for (int c = 0; c < CDIM; c++) {
        float v = xp[(long)c * HWD];
        yp[(long)c * HWD] = (v - mu) * inv * w[c] + b[c];
    }
}

// ---------------- pad ffn_out weight 64x170 -> 64x176 (zero fill) ----------------
__global__ void padw_kernel(const float* __restrict__ w, float* __restrict__ wp)
{
    int i = blockIdx.x * 256 + threadIdx.x;
    if (i >= 64 * 176) return;
    int r = i / 176, c = i - r * 176;
    wp[i] = (c < 170) ? w[r * 170 + c] : 0.f;
}

// ---------------- row-oriented depthwise 3x3 + optional in-place row L2 normalize ------
__global__ void dwconv_rows_kernel(const float* __restrict__ x, const float* __restrict__ wt,
                                   const float* __restrict__ bias, float* __restrict__ y,
                                   int OC, int normCh)
{
    long bidx = blockIdx.x;
    int hb = (int)(bidx & 63) * 4;
    long bc = bidx >> 6;
    int c = (int)(bc % OC);
    int rowid = threadIdx.x >> 6;
    int t = threadIdx.x & 63;
    int h = hb + rowid;
    int w4 = t * 4;
    const float* xp = x + (bc << 16);
    float b0 = bias[c];
    float acc0 = b0, acc1 = b0, acc2 = b0, acc3 = b0;
#pragma unroll
    for (int kh = -1; kh <= 1; kh++) {
        int hh = h + kh;
        if (hh < 0 || hh >= HH) continue;
        const float* row = xp + hh * WW;
        float vm1 = (w4 > 0)      ? row[w4 - 1] : 0.f;
        float4 v  = *reinterpret_cast<const float4*>(&row[w4]);
        float vp4 = (w4 + 4 < WW) ? row[w4 + 4] : 0.f;
        float vals[6] = {vm1, v.x, v.y, v.z, v.w, vp4};
        const float* wr = wt + c * 9 + (kh + 1) * 3;
#pragma unroll
        for (int kw = 0; kw < 3; kw++) {
            float g = wr[kw];
            acc0 = fmaf(g, vals[kw + 0], acc0);
            acc1 = fmaf(g, vals[kw + 1], acc1);
            acc2 = fmaf(g, vals[kw + 2], acc2);
            acc3 = fmaf(g, vals[kw + 3], acc3);
        }
    }
    if (c < normCh) {
        float s = acc0 * acc0 + acc1 * acc1 + acc2 * acc2 + acc3 * acc3;
#pragma unroll
        for (int o = 16; o > 0; o >>= 1) s += __shfl_down_sync(0xffffffffu, s, o);
        __shared__ float part[8];
        int warp = threadIdx.x >> 5, lane = threadIdx.x & 31;
        if (lane == 0) part[warp] = s;
        __syncthreads();
        float inv = 1.f / fmaxf(sqrtf(part[rowid * 2] + part[rowid * 2 + 1]), 1e-12f);
        acc0 *= inv; acc1 *= inv; acc2 *= inv; acc3 *= inv;
    }
    *reinterpret_cast<float4*>(&y[(bc << 16) + h * WW + w4]) = make_float4(acc0, acc1, acc2, acc3);
}

// ---------------- fused FFN depthwise 3x3 + GELU gate ----------------
__global__ void dwconv_gate_kernel(const float* __restrict__ x, const float* __restrict__ wt,
                                   const float* __restrict__ bias, float* __restrict__ g)
{
    long idx = (long)blockIdx.x * blockDim.x + threadIdx.x;
    long total = (long)BATCH * HID * (HWD / 4);
    if (idx >= total) return;
    int w4 = (int)(idx & 63) * 4;
    int h  = (int)((idx >> 6) & 255);
    long bc = idx >> 14;
    int c = (int)(bc % HID);
    int b = (int)(bc / HID);
    const float* xp1 = x + ((long)b * HID2 + c) * HWD;
    const float* xp2 = xp1 + (long)HID * HWD;
    float bb1 = bias[c], bb2 = bias[c + HID];
    float a0 = bb1, a1 = bb1, a2 = bb1, a3 = bb1;
    float c0 = bb2, c1 = bb2, c2 = bb2, c3 = bb2;
    const float* w1 = wt + c * 9;
    const float* w2 = wt + (c + HID) * 9;
#pragma unroll
    for (int kh = -1; kh <= 1; kh++) {
        int hh = h + kh;
        if (hh < 0 || hh >= HH) continue;
        {
            const float* row = xp1 + hh * WW;
            float vm1 = (w4 > 0)      ? row[w4 - 1] : 0.f;
            float4 v  = *reinterpret_cast<const float4*>(&row[w4]);
            float vp4 = (w4 + 4 < WW) ? row[w4 + 4] : 0.f;
            float vals[6] = {vm1, v.x, v.y, v.z, v.w, vp4};
            const float* wr = w1 + (kh + 1) * 3;
#pragma unroll
            for (int kw = 0; kw < 3; kw++) {
                float gg = wr[kw];
                a0 = fmaf(gg, vals[kw + 0], a0);
                a1 = fmaf(gg, vals[kw + 1], a1);
                a2 = fmaf(gg, vals[kw + 2], a2);
                a3 = fmaf(gg, vals[kw + 3], a3);
            }
        }
        {
            const float* row = xp2 + hh * WW;
            float vm1 = (w4 > 0)      ? row[w4 - 1] : 0.f;
            float4 v  = *reinterpret_cast<const float4*>(&row[w4]);
            float vp4 = (w4 + 4 < WW) ? row[w4 + 4] : 0.f;
            float vals[6] = {vm1, v.x, v.y, v.z, v.w, vp4};
            const float* wr = w2 + (kh + 1) * 3;
#pragma unroll
            for (int kw = 0; kw < 3; kw++) {
                float gg = wr[kw];
                c0 = fmaf(gg, vals[kw + 0], c0);
                c1 = fmaf(gg, vals[kw + 1], c1);
                c2 = fmaf(gg, vals[kw + 2], c2);
                c3 = fmaf(gg, vals[kw + 3], c3);
            }
        }
    }
    const float k = 0.70710678118654752f;
    float4 o;
    o.x = 0.5f * a0 * (1.0f + erff(a0 * k)) * c0;
    o.y = 0.5f * a1 * (1.0f + erff(a1 * k)) * c1;
    o.z = 0.5f * a2 * (1.0f + erff(a2 * k)) * c2;
    o.w = 0.5f * a3 * (1.0f + erff(a3 * k)) * c3;
    *reinterpret_cast<float4*>(&g[((long)b * HID + c) * HWD + h * WW + w4]) = o;
}

// ---------------- hxh inverse norm: per (b,h) over (c,w) ----------------
__global__ void hnorm_kernel(const float* __restrict__ src, float* __restrict__ out)
{
    int b = blockIdx.y, h = blockIdx.x;
    int t = threadIdx.x;
    const float* p = src + (long)b * (3 * CDIM) * HWD + (long)h * WW + t;
    float s = 0.f;
#pragma unroll
    for (int c = 0; c < CDIM; c++) { float v = p[(long)c * HWD]; s += v * v; }
    __shared__ float red[256];
    red[t] = s; __syncthreads();
    for (int o = 128; o > 0; o >>= 1) { if (t < o) red[t] += red[t + o]; __syncthreads(); }
    if (t == 0) out[b * HH + h] = 1.f / fmaxf(sqrtf(red[0]), 1e-12f);
}

// ---------------- softmax over last dim of [B, 256, 256] ----------------
__global__ void softmax_kernel(float* __restrict__ attn, const float* __restrict__ temp,
                               const float* __restrict__ sq, const float* __restrict__ sk)
{
    int b = blockIdx.y;
    int r = blockIdx.x;
    float* row = attn + ((long)b * WW + r) * WW;
    int t = threadIdx.x;
    float v = row[t] * temp[0];
    if (sq) v *= sq[b * WW + r] * sk[b * WW + t];
    __shared__ float red[256];
    red[t] = v; __syncthreads();
    for (int o = 128; o > 0; o >>= 1) { if (t < o) red[t] = fmaxf(red[t], red[t + o]); __syncthreads(); }
    float mx = red[0]; __syncthreads();
    float e = __expf(v - mx);
    red[t] = e; __syncthreads();
    for (int o = 128; o > 0; o >>= 1) { if (t < o) red[t] += red[t + o]; __syncthreads(); }
    row[t] = e * (1.f / red[0]);
}

// ---------------- dedicated gram kernel (unchanged from R4) ----------------
template<int L>
__global__ void __launch_bounds__(256, 2) gram_kernel(
    const float* __restrict__ Qb, const float* __restrict__ Kb,
    float* __restrict__ Cb, int KS)
{
    constexpr int P0 = 136;
    constexpr int P1 = 20;
    constexpr int SSZ = (L == 0) ? 2 * 16 * P0 : 2 * 128 * P1;
    __shared__ __align__(16) float As[SSZ];
    __shared__ __align__(16) float Bs[SSZ];

    int z = blockIdx.z;
    int b = z / KS, ks = z - b * KS;
    const float* Q = Qb + (long)b * (3 * CDIM * HWD);
    const float* Kp = Kb + (long)b * (3 * CDIM * HWD);
    float* C = Cb + (long)b * 65536;
    int m0 = blockIdx.x * 128, n0 = blockIdx.y * 128;
    int kchunk = 16384 / KS;
    int kbeg = ks * kchunk, kend = kbeg + kchunk;

    int tid = threadIdx.x, lane = tid & 31, warp = tid >> 5;
    int wm = warp & 1, wn = warp >> 1;
    int r = lane >> 2, c = lane & 3;

    unsigned sA = (unsigned)__cvta_generic_to_shared(As);
    unsigned sB = (unsigned)__cvta_generic_to_shared(Bs);

    auto loadStage = [&](int buf, int k0) {
        if (L == 0) {
            int row = tid >> 4;
            int q   = tid & 15;
            const float* gA = Q  + (long)(k0 + row) * 256 + m0;
            const float* gB = Kp + (long)(k0 + row) * 256 + n0;
            unsigned dA = sA + ((buf * 16 + row) * P0) * 4;
            unsigned dB = sB + ((buf * 16 + row) * P0) * 4;
            CPA16(dA + q * 16,        gA + q * 4);
            CPA16(dA + (q + 16) * 16, gA + (q + 16) * 4);
            CPA16(dB + q * 16,        gB + q * 4);
            CPA16(dB + (q + 16) * 16, gB + (q + 16) * 4);
        } else {
            int m  = tid >> 1;
            int qi = (tid & 1) * 2;
            long kb = (long)(k0 >> 8) * 65536 + (k0 & 255);
            const float* gA = Q  + (long)(m0 + m) * 256 + kb;
            const float* gB = Kp + (long)(n0 + m) * 256 + kb;
            unsigned dA = sA + ((buf * 128 + m) * P1) * 4;
            unsigned dB = sB + ((buf * 128 + m) * P1) * 4;
            CPA16(dA + qi * 16,       gA + qi * 4);
            CPA16(dA + (qi + 1) * 16, gA + (qi + 1) * 4);
            CPA16(dB + qi * 16,       gB + qi * 4);
            CPA16(dB + (qi + 1) * 16, gB + (qi + 1) * 4);
        }
    };

    float acc[16][4];
#pragma unroll
    for (int i = 0; i < 16; i++)
#pragma unroll
        for (int j = 0; j < 4; j++) acc[i][j] = 0.f;

    loadStage(0, kbeg);
    asm volatile("cp.async.commit_group;");
    int buf = 0;

    for (int k0 = kbeg; k0 < kend; k0 += 16) {
        int kn = k0 + 16;
        if (kn < kend) loadStage(buf ^ 1, kn);
        asm volatile("cp.async.commit_group;");
        asm volatile("cp.async.wait_group 1;");
        __syncthreads();

        const float* A_ = As + (L == 0 ? buf * 16 * P0 : buf * 128 * P1);
        const float* B_ = Bs + (L == 0 ? buf * 16 * P0 : buf * 128 * P1);
#pragma unroll
        for (int ks2 = 0; ks2 < 2; ks2++) {
            int kc = ks2 * 8 + c;
            unsigned a0[4], a1[4], a2[4], a3[4];
#pragma unroll
            for (int mt = 0; mt < 4; mt++) {
                int mr = wm * 64 + mt * 16 + r;
                if (L == 0) {
                    a0[mt] = __float_as_uint(A_[kc * P0 + mr]);
                    a1[mt] = __float_as_uint(A_[kc * P0 + mr + 8]);
                    a2[mt] = __float_as_uint(A_[(kc + 4) * P0 + mr]);
                    a3[mt] = __float_as_uint(A_[(kc + 4) * P0 + mr + 8]);
                } else {
                    a0[mt] = __float_as_uint(A_[mr * P1 + kc]);
                    a1[mt] = __float_as_uint(A_[(mr + 8) * P1 + kc]);
                    a2[mt] = __float_as_uint(A_[mr * P1 + kc + 4]);
                    a3[mt] = __float_as_uint(A_[(mr + 8) * P1 + kc + 4]);
                }
            }
#pragma unroll
            for (int j = 0; j < 4; j++) {
                int nn = wn * 32 + j * 8 + r;
                unsigned b0, b1;
                if (L == 0) {
                    b0 = __float_as_uint(B_[kc * P0 + nn]);
                    b1 = __float_as_uint(B_[(kc + 4) * P0 + nn]);
                } else {
                    b0 = __float_as_uint(B_[nn * P1 + kc]);
                    b1 = __float_as_uint(B_[nn * P1 + kc + 4]);
                }
#pragma unroll
                for (int mt = 0; mt < 4; mt++)
                    mma8(acc[mt * 4 + j], a0[mt], a1[mt], a2[mt], a3[mt], b0, b1);
            }
        }
        __syncthreads();
        buf ^= 1;
    }

#pragma unroll
    for (int mt = 0; mt < 4; mt++) {
#pragma unroll
        for (int j = 0; j < 4; j++) {
            int mrow = m0 + wm * 64 + mt * 16 + r;
            int n    = n0 + wn * 32 + j * 8 + c * 2;
            float* ci = acc[mt * 4 + j];
            atomicAdd(&C[(long)mrow * 256 + n],           ci[0]);
            atomicAdd(&C[(long)mrow * 256 + n + 1],       ci[1]);
            atomicAdd(&C[(long)(mrow + 8) * 256 + n],     ci[2]);
            atomicAdd(&C[(long)(mrow + 8) * 256 + n + 1], ci[3]);
        }
    }
}

// ---------------- unified cp.async tf32 GEMM: BM=128, BN=64, BK=16, 128 threads -------
// C[m,n] = sum_k A[m*lda + k] * B[k*sbk + n]  (+bias[m], +res)
// A rows clamped to M-1 (results masked in epilogue). K = kit16*16 (A padded if needed).
// z: z1 = z/zdiv, z2 = z%zdiv; pointer offsets via strides.
__global__ void __launch_bounds__(128, 4) mma2_kernel(
    const float* __restrict__ A, const float* __restrict__ B, float* __restrict__ C,
    int M, int kit16, int lda, long sbk, int ldc, int zdiv,
    long sA1, long sA2, long sB1, long sB2, long sC1, long sC2,
    const float* __restrict__ bias,
    const float* __restrict__ res, long sR1, long sR2)
{
    constexpr int PA = 20;
    constexpr int PB = 68;
    __shared__ __align__(16) float As[2 * 128 * PA];
    __shared__ __align__(16) float Bs[2 * 16 * PB];

    int z = blockIdx.z;
    int z1 = z / zdiv, z2 = z - z1 * zdiv;
    const float* Ap = A + (long)z1 * sA1 + (long)z2 * sA2;
    const float* Bp = B + (long)z1 * sB1 + (long)z2 * sB2;
    float*       Cp = C + (long)z1 * sC1 + (long)z2 * sC2;

    int m0 = blockIdx.x * 128;
    int n0 = blockIdx.y * 64;

    int tid = threadIdx.x, lane = tid & 31, warp = tid >> 5;
    int r = lane >> 2, c = lane & 3;

    unsigned sAu = (unsigned)__cvta_generic_to_shared(As);
    unsigned sBu = (unsigned)__cvta_generic_to_shared(Bs);

    auto loadStage = [&](int buf, int kit) {
        int k0 = kit * 16;
        // A: 128 m x 16 k  (4 chunks of 16B per thread)
#pragma unroll
        for (int i = 0; i < 4; i++) {
            int q = tid + i * 128;
            int m = q >> 2, k4 = (q & 3) * 4;
            int gm = min(m0 + m, M - 1);
            CPA16(sAu + ((buf * 128 + m) * PA + k4) * 4, Ap + (long)gm * lda + k0 + k4);
        }
        // B: 16 k x 64 n  (2 chunks per thread)
#pragma unroll
        for (int i = 0; i < 2; i++) {
            int q = tid + i * 128;
            int k = q >> 4, n4 = (q & 15) * 4;
            CPA16(sBu + ((buf * 16 + k) * PB + n4) * 4, Bp + (long)(k0 + k) * sbk + n0 + n4);
        }
    };

    float acc[16][4];
#pragma unroll
    for (int i = 0; i < 16; i++)
#pragma unroll
        for (int j = 0; j < 4; j++) acc[i][j] = 0.f;

    loadStage(0, 0);
    asm volatile("cp.async.commit_group;");
    int buf = 0;

    for (int kit = 0; kit < kit16; kit++) {
        if (kit + 1 < kit16) loadStage(buf ^ 1, kit + 1);
        asm volatile("cp.async.commit_group;");
        asm volatile("cp.async.wait_group 1;");
        __syncthreads();

        const float* A_ = As + buf * 128 * PA;
        const float* B_ = Bs + buf * 16 * PB;
#pragma unroll
        for (int ks2 = 0; ks2 < 2; ks2++) {
            int kc = ks2 * 8 + c;
            unsigned a0[2], a1[2], a2[2], a3[2];
#pragma unroll
            for (int mt = 0; mt < 2; mt++) {
                int mr = warp * 32 + mt * 16 + r;
                a0[mt] = __float_as_uint(A_[mr * PA + kc]);
                a1[mt] = __float_as_uint(A_[(mr + 8) * PA + kc]);
                a2[mt] = __float_as_uint(A_[mr * PA + kc + 4]);
                a3[mt] = __float_as_uint(A_[(mr + 8) * PA + kc + 4]);
            }
#pragma unroll
            for (int j = 0; j < 8; j++) {
                int nn = j * 8 + r;
                unsigned b0 = __float_as_uint(B_[kc * PB + nn]);
                unsigned b1 = __float_as_uint(B_[(kc + 4) * PB + nn]);
#pragma unroll
                for (int mt = 0; mt < 2; mt++)
                    mma8(acc[mt * 8 + j], a0[mt], a1[mt], a2[mt], a3[mt], b0, b1);
            }
        }
        __syncthreads();
        buf ^= 1;
    }

    const float* Rp = res ? res + (long)z1 * sR1 + (long)z2 * sR2 : nullptr;
#pragma unroll
    for (int mt = 0; mt < 2; mt++) {
#pragma unroll
        for (int j = 0; j < 8; j++) {
            int mA = m0 + warp * 32 + mt * 16 + r;
            int n  = n0 + j * 8 + c * 2;
            float* ci = acc[mt * 8 + j];
#pragma unroll
            for (int half = 0; half < 2; half++) {
                int mrow = mA + half * 8;
                if (mrow >= M) continue;
                float bv = bias ? bias[mrow] : 0.f;
                float v0 = ci[half * 2 + 0] + bv;
                float v1 = ci[half * 2 + 1] + bv;
                long off = (long)mrow * ldc + n;
                if (Rp) { v0 += Rp[off]; v1 += Rp[off + 1]; }
                *reinterpret_cast<float2*>(&Cp[off]) = make_float2(v0, v1);
            }
        }
    }
}

extern "C" void kernel_launch(void* const* d_in, const int* in_sizes, int n_in,
                              void* d_out, int out_size)
{
    const float* x        = (const float*)d_in[0];
    const float* w_ln_w   = (const float*)d_in[2];
    const float* w_ln_b   = (const float*)d_in[3];
    const float* w_qkv_w  = (const float*)d_in[4];
    const float* w_qkv_b  = (const float*)d_in[5];
    const float* w_dw_w   = (const float*)d_in[6];
    const float* w_dw_b   = (const float*)d_in[7];
    const float* w_proj_w = (const float*)d_in[8];
    const float* w_proj_b = (const float*)d_in[9];
    const float* w_temp   = (const float*)d_in[10];
    const float* h_ln_w   = (const float*)d_in[11];
    const float* h_ln_b   = (const float*)d_in[12];
    const float* h_qkv_w  = (const float*)d_in[13];
    const float* h_qkv_b  = (const float*)d_in[14];
    const float* h_dw_w   = (const float*)d_in[15];
    const float* h_dw_b   = (const float*)d_in[16];
    const float* h_proj_w = (const float*)d_in[17];
    const float* h_proj_b = (const float*)d_in[18];
    const float* h_temp   = (const float*)d_in[19];
    const float* n2_w     = (const float*)d_in[20];
    const float* n2_b     = (const float*)d_in[21];
    const float* ffn_in_w = (const float*)d_in[22];
    const float* ffn_in_b = (const float*)d_in[23];
    const float* ffn_dw_w = (const float*)d_in[24];
    const float* ffn_dw_b = (const float*)d_in[25];
    const float* ffn_out_w= (const float*)d_in[26];
    const float* ffn_out_b= (const float*)d_in[27];
    float* out = (float*)d_out;

    float *bufA, *bufM, *bufZ, *qkv1, *qkv2, *attn, *sq, *sk, *wpad;
    cudaGetSymbolAddress((void**)&bufA, g_bufA);
    cudaGetSymbolAddress((void**)&bufM, g_bufM);
    cudaGetSymbolAddress((void**)&bufZ, g_bufZ);
    cudaGetSymbolAddress((void**)&qkv1, g_qkv1);
    cudaGetSymbolAddress((void**)&qkv2, g_qkv2);
    cudaGetSymbolAddress((void**)&attn, g_attn);
    cudaGetSymbolAddress((void**)&sq,   g_sq);
    cudaGetSymbolAddress((void**)&sk,   g_sk);
    cudaGetSymbolAddress((void**)&wpad, g_wpad);

    const long sX = (long)CDIM * HWD;
    const long sQ = (long)3 * CDIM * HWD;
    const int KS = 32;

    padw_kernel<<<(64 * 176 + 255) / 256, 256>>>(ffn_out_w, wpad);

    // ================= attention (WxW) =================
    ln_kernel<<<(BATCH * HWD) / 256, 256>>>(x, w_ln_w, w_ln_b, bufA);
    // qkv = W[192,64] @ ln : grid (2, 1024, 4)
    mma2_kernel<<<dim3(2, 1024, BATCH), 128>>>(w_qkv_w, bufA, qkv1,
        192, 4, 64, HWD, HWD, 1, 0,0, sX,0, sQ,0, w_qkv_b, nullptr, 0,0);
    dwconv_rows_kernel<<<BATCH*192*64, 256>>>(qkv1, w_dw_w, w_dw_b, qkv2, 192, 128);
    cudaMemsetAsync(attn, 0, (size_t)BATCH * WW * WW * sizeof(float));
    gram_kernel<0><<<dim3(2, 2, BATCH * KS), 256>>>(qkv2, qkv2 + 64*(long)HWD, attn, KS);
    softmax_kernel<<<dim3(WW, BATCH), 256>>>(attn, w_temp, nullptr, nullptr);
    // AV: v[16384,256] @ attn[256,256]
    mma2_kernel<<<dim3(128, 4, BATCH), 128>>>(qkv2 + 128*(long)HWD, attn, bufA,
        CHROWS, 16, 256, 256, 256, 1, sQ,0, (long)WW*WW,0, sX,0, nullptr, nullptr, 0,0);
    // proj + residual x -> bufM
    mma2_kernel<<<dim3(1, 1024, BATCH), 128>>>(w_proj_w, bufA, bufM,
        64, 4, 64, HWD, HWD, 1, 0,0, sX,0, sX,0, w_proj_b, x, sX,0);

    // ================= attention (HxH) =================
    ln_kernel<<<(BATCH * HWD) / 256, 256>>>(bufM, h_ln_w, h_ln_b, bufA);
    mma2_kernel<<<dim3(2, 1024, BATCH), 128>>>(h_qkv_w, bufA, qkv1,
        192, 4, 64, HWD, HWD, 1, 0,0, sX,0, sQ,0, h_qkv_b, nullptr, 0,0);
    dwconv_rows_kernel<<<BATCH*192*64, 256>>>(qkv1, h_dw_w, h_dw_b, qkv2, 192, 0);
    hnorm_kernel<<<dim3(HH, BATCH), 256>>>(qkv2,                sq);
    hnorm_kernel<<<dim3(HH, BATCH), 256>>>(qkv2 + 64*(long)HWD, sk);
    cudaMemsetAsync(attn, 0, (size_t)BATCH * WW * WW * sizeof(float));
    gram_kernel<1><<<dim3(2, 2, BATCH * KS), 256>>>(qkv2, qkv2 + 64*(long)HWD, attn, KS);
    softmax_kernel<<<dim3(WW, BATCH), 256>>>(attn, h_temp, sq, sk);
    // AV: per (b,c): attn[256,256] @ v[c][256,256]
    mma2_kernel<<<dim3(2, 4, BATCH * 64), 128>>>(attn, qkv2 + 128*(long)HWD, bufA,
        256, 16, 256, 256, 256, 64, (long)WW*WW,0, sQ,(long)HWD, sX,(long)HWD,
        nullptr, nullptr, 0,0);
    // proj + residual m -> bufZ
    mma2_kernel<<<dim3(1, 1024, BATCH), 128>>>(h_proj_w, bufA, bufZ,
        64, 4, 64, HWD, HWD, 1, 0,0, sX,0, sX,0, h_proj_b, bufM, sX,0);

    // ================= FFN =================
    ln_kernel<<<(BATCH * HWD) / 256, 256>>>(bufZ, n2_w, n2_b, bufA);
    mma2_kernel<<<dim3(3, 1024, BATCH), 128>>>(ffn_in_w, bufA, qkv1,
        HID2, 4, 64, HWD, HWD, 1, 0,0, sX,0, (long)HID2*HWD,0, ffn_in_b, nullptr, 0,0);
    dwconv_gate_kernel<<<((long)BATCH*HID*HWD/4 + 255)/256, 256>>>(qkv1, ffn_dw_w, ffn_dw_b, qkv2);
    // out = Wout(padded)[64,176] @ gated[170(176),HWD] + bias + z
    mma2_kernel<<<dim3(1, 1024, BATCH), 128>>>(wpad, qkv2, out,
        64, 11, 176, HWD, HWD, 1, 0,0, (long)HID*HWD,0, sX,0, ffn_out_b, bufZ, sX,0);
}

// round 6
// speedup vs baseline: 2.7691x; 2.7691x over previous
#include <cuda_runtime.h>
#include <math.h>

#define BATCH 4
#define CDIM  64
#define HH    256
#define WW    256
#define HWD   65536          // H*W
#define CHROWS 16384         // C*H
#define HID   170
#define HID2  340

// ---------------- scratch (device globals; no allocations allowed) ----------------
__device__ float g_bufA[(size_t)BATCH * CDIM * HWD];
__device__ float g_bufM[(size_t)BATCH * CDIM * HWD];
__device__ float g_bufZ[(size_t)BATCH * CDIM * HWD];
__device__ float g_qkv1[(size_t)BATCH * HID2 * HWD];
__device__ float g_qkv2[(size_t)BATCH * HID2 * HWD];
__device__ float g_attn[(size_t)BATCH * WW * WW];
__device__ float g_sq[BATCH * HH];
__device__ float g_sk[BATCH * HH];
__device__ float g_wpad[64 * 176];

// ---------------- helpers ----------------
__device__ __forceinline__ void mma8(float* d, unsigned a0, unsigned a1, unsigned a2, unsigned a3,
                                     unsigned b0, unsigned b1) {
    asm volatile(
        "mma.sync.aligned.m16n8k8.row.col.f32.tf32.tf32.f32 "
        "{%0,%1,%2,%3},{%4,%5,%6,%7},{%8,%9},{%0,%1,%2,%3};\n"
        : "+f"(d[0]), "+f"(d[1]), "+f"(d[2]), "+f"(d[3])
        : "r"(a0), "r"(a1), "r"(a2), "r"(a3), "r"(b0), "r"(b1));
}
#define CPA16(dst_u32, src_ptr) \
    asm volatile("cp.async.cg.shared.global [%0], [%1], 16;" :: "r"(dst_u32), "l"(src_ptr))

// ---------------- LayerNorm over channel dim (per pixel) ----------------
__global__ void ln_kernel(const float* __restrict__ x, const float* __restrict__ w,
                          const float* __restrict__ b, float* __restrict__ y)
{
    long p = (long)blockIdx.x * blockDim.x + threadIdx.x;
    if (p >= (long)BATCH * HWD) return;
    int bb  = (int)(p >> 16);
    int pix = (int)(p & (HWD - 1));
    const float* xp = x + (long)bb * CDIM * HWD + pix;
    float s = 0.f, s2 = 0.f;
#pragma unroll
    for (int c = 0; c < CDIM; c++) {
        float v = xp[(long)c * HWD];
        s += v; s2 += v * v;
    }
    float mu  = s * (1.0f / CDIM);
    float var = s2 * (1.0f / CDIM) - mu * mu;
    float inv = rsqrtf(var + 1e-5f);
    float* yp = y + (long)bb * CDIM * HWD + pix;
#pragma unroll
    for (int c = 0; c < CDIM; c++) {
        float v = xp[(long)c * HWD];
        yp[(long)c * HWD] = (v - mu) * inv * w[c] + b[c];
    }
}

// ---------------- pad ffn_out weight 64x170 -> 64x176 (zero fill) ----------------
__global__ void padw_kernel(const float* __restrict__ w, float* __restrict__ wp)
{
    int i = blockIdx.x * 256 + threadIdx.x;
    if (i >= 64 * 176) return;
    int r = i / 176, c = i - r * 176;
    wp[i] = (c < 170) ? w[r * 170 + c] : 0.f;
}

// ---------------- row-oriented depthwise 3x3 + optional in-place row L2 normalize ------
__global__ void dwconv_rows_kernel(const float* __restrict__ x, const float* __restrict__ wt,
                                   const float* __restrict__ bias, float* __restrict__ y,
                                   int OC, int normCh)
{
    long bidx = blockIdx.x;
    int hb = (int)(bidx & 63) * 4;
    long bc = bidx >> 6;
    int c = (int)(bc % OC);
    int rowid = threadIdx.x >> 6;
    int t = threadIdx.x & 63;
    int h = hb + rowid;
    int w4 = t * 4;
    const float* xp = x + (bc << 16);
    float b0 = bias[c];
    float acc0 = b0, acc1 = b0, acc2 = b0, acc3 = b0;
#pragma unroll
    for (int kh = -1; kh <= 1; kh++) {
        int hh = h + kh;
        if (hh < 0 || hh >= HH) continue;
        const float* row = xp + hh * WW;
        float vm1 = (w4 > 0)      ? row[w4 - 1] : 0.f;
        float4 v  = *reinterpret_cast<const float4*>(&row[w4]);
        float vp4 = (w4 + 4 < WW) ? row[w4 + 4] : 0.f;
        float vals[6] = {vm1, v.x, v.y, v.z, v.w, vp4};
        const float* wr = wt + c * 9 + (kh + 1) * 3;
#pragma unroll
        for (int kw = 0; kw < 3; kw++) {
            float g = wr[kw];
            acc0 = fmaf(g, vals[kw + 0], acc0);
            acc1 = fmaf(g, vals[kw + 1], acc1);
            acc2 = fmaf(g, vals[kw + 2], acc2);
            acc3 = fmaf(g, vals[kw + 3], acc3);
        }
    }
    if (c < normCh) {
        float s = acc0 * acc0 + acc1 * acc1 + acc2 * acc2 + acc3 * acc3;
#pragma unroll
        for (int o = 16; o > 0; o >>= 1) s += __shfl_down_sync(0xffffffffu, s, o);
        __shared__ float part[8];
        int warp = threadIdx.x >> 5, lane = threadIdx.x & 31;
        if (lane == 0) part[warp] = s;
        __syncthreads();
        float inv = 1.f / fmaxf(sqrtf(part[rowid * 2] + part[rowid * 2 + 1]), 1e-12f);
        acc0 *= inv; acc1 *= inv; acc2 *= inv; acc3 *= inv;
    }
    *reinterpret_cast<float4*>(&y[(bc << 16) + h * WW + w4]) = make_float4(acc0, acc1, acc2, acc3);
}

// ---------------- fused FFN depthwise 3x3 + GELU gate ----------------
__global__ void dwconv_gate_kernel(const float* __restrict__ x, const float* __restrict__ wt,
                                   const float* __restrict__ bias, float* __restrict__ g)
{
    long idx = (long)blockIdx.x * blockDim.x + threadIdx.x;
    long total = (long)BATCH * HID * (HWD / 4);
    if (idx >= total) return;
    int w4 = (int)(idx & 63) * 4;
    int h  = (int)((idx >> 6) & 255);
    long bc = idx >> 14;
    int c = (int)(bc % HID);
    int b = (int)(bc / HID);
    const float* xp1 = x + ((long)b * HID2 + c) * HWD;
    const float* xp2 = xp1 + (long)HID * HWD;
    float bb1 = bias[c], bb2 = bias[c + HID];
    float a0 = bb1, a1 = bb1, a2 = bb1, a3 = bb1;
    float c0 = bb2, c1 = bb2, c2 = bb2, c3 = bb2;
    const float* w1 = wt + c * 9;
    const float* w2 = wt + (c + HID) * 9;
#pragma unroll
    for (int kh = -1; kh <= 1; kh++) {
        int hh = h + kh;
        if (hh < 0 || hh >= HH) continue;
        {
            const float* row = xp1 + hh * WW;
            float vm1 = (w4 > 0)      ? row[w4 - 1] : 0.f;
            float4 v  = *reinterpret_cast<const float4*>(&row[w4]);
            float vp4 = (w4 + 4 < WW) ? row[w4 + 4] : 0.f;
            float vals[6] = {vm1, v.x, v.y, v.z, v.w, vp4};
            const float* wr = w1 + (kh + 1) * 3;
#pragma unroll
            for (int kw = 0; kw < 3; kw++) {
                float gg = wr[kw];
                a0 = fmaf(gg, vals[kw + 0], a0);
                a1 = fmaf(gg, vals[kw + 1], a1);
                a2 = fmaf(gg, vals[kw + 2], a2);
                a3 = fmaf(gg, vals[kw + 3], a3);
            }
        }
        {
            const float* row = xp2 + hh * WW;
            float vm1 = (w4 > 0)      ? row[w4 - 1] : 0.f;
            float4 v  = *reinterpret_cast<const float4*>(&row[w4]);
            float vp4 = (w4 + 4 < WW) ? row[w4 + 4] : 0.f;
            float vals[6] = {vm1, v.x, v.y, v.z, v.w, vp4};
            const float* wr = w2 + (kh + 1) * 3;
#pragma unroll
            for (int kw = 0; kw < 3; kw++) {
                float gg = wr[kw];
                c0 = fmaf(gg, vals[kw + 0], c0);
                c1 = fmaf(gg, vals[kw + 1], c1);
                c2 = fmaf(gg, vals[kw + 2], c2);
                c3 = fmaf(gg, vals[kw + 3], c3);
            }
        }
    }
    const float k = 0.70710678118654752f;
    float4 o;
    o.x = 0.5f * a0 * (1.0f + erff(a0 * k)) * c0;
    o.y = 0.5f * a1 * (1.0f + erff(a1 * k)) * c1;
    o.z = 0.5f * a2 * (1.0f + erff(a2 * k)) * c2;
    o.w = 0.5f * a3 * (1.0f + erff(a3 * k)) * c3;
    *reinterpret_cast<float4*>(&g[((long)b * HID + c) * HWD + h * WW + w4]) = o;
}

// ---------------- hxh inverse norm: per (b,h) over (c,w) ----------------
__global__ void hnorm_kernel(const float* __restrict__ src, float* __restrict__ out)
{
    int b = blockIdx.y, h = blockIdx.x;
    int t = threadIdx.x;
    const float* p = src + (long)b * (3 * CDIM) * HWD + (long)h * WW + t;
    float s = 0.f;
#pragma unroll
    for (int c = 0; c < CDIM; c++) { float v = p[(long)c * HWD]; s += v * v; }
    __shared__ float red[256];
    red[t] = s; __syncthreads();
    for (int o = 128; o > 0; o >>= 1) { if (t < o) red[t] += red[t + o]; __syncthreads(); }
    if (t == 0) out[b * HH + h] = 1.f / fmaxf(sqrtf(red[0]), 1e-12f);
}

// ---------------- softmax over last dim of [B, 256, 256] ----------------
__global__ void softmax_kernel(float* __restrict__ attn, const float* __restrict__ temp,
                               const float* __restrict__ sq, const float* __restrict__ sk)
{
    int b = blockIdx.y;
    int r = blockIdx.x;
    float* row = attn + ((long)b * WW + r) * WW;
    int t = threadIdx.x;
    float v = row[t] * temp[0];
    if (sq) v *= sq[b * WW + r] * sk[b * WW + t];
    __shared__ float red[256];
    red[t] = v; __syncthreads();
    for (int o = 128; o > 0; o >>= 1) { if (t < o) red[t] = fmaxf(red[t], red[t + o]); __syncthreads(); }
    float mx = red[0]; __syncthreads();
    float e = __expf(v - mx);
    red[t] = e; __syncthreads();
    for (int o = 128; o > 0; o >>= 1) { if (t < o) red[t] += red[t + o]; __syncthreads(); }
    row[t] = e * (1.f / red[0]);
}

// ---------------- dedicated gram kernel (unchanged) ----------------
template<int L>
__global__ void __launch_bounds__(256, 2) gram_kernel(
    const float* __restrict__ Qb, const float* __restrict__ Kb,
    float* __restrict__ Cb, int KS)
{
    constexpr int P0 = 136;
    constexpr int P1 = 20;
    constexpr int SSZ = (L == 0) ? 2 * 16 * P0 : 2 * 128 * P1;
    __shared__ __align__(16) float As[SSZ];
    __shared__ __align__(16) float Bs[SSZ];

    int z = blockIdx.z;
    int b = z / KS, ks = z - b * KS;
    const float* Q = Qb + (long)b * (3 * CDIM * HWD);
    const float* Kp = Kb + (long)b * (3 * CDIM * HWD);
    float* C = Cb + (long)b * 65536;
    int m0 = blockIdx.x * 128, n0 = blockIdx.y * 128;
    int kchunk = 16384 / KS;
    int kbeg = ks * kchunk, kend = kbeg + kchunk;

    int tid = threadIdx.x, lane = tid & 31, warp = tid >> 5;
    int wm = warp & 1, wn = warp >> 1;
    int r = lane >> 2, c = lane & 3;

    unsigned sA = (unsigned)__cvta_generic_to_shared(As);
    unsigned sB = (unsigned)__cvta_generic_to_shared(Bs);

    auto loadStage = [&](int buf, int k0) {
        if (L == 0) {
            int row = tid >> 4;
            int q   = tid & 15;
            const float* gA = Q  + (long)(k0 + row) * 256 + m0;
            const float* gB = Kp + (long)(k0 + row) * 256 + n0;
            unsigned dA = sA + ((buf * 16 + row) * P0) * 4;
            unsigned dB = sB + ((buf * 16 + row) * P0) * 4;
            CPA16(dA + q * 16,        gA + q * 4);
            CPA16(dA + (q + 16) * 16, gA + (q + 16) * 4);
            CPA16(dB + q * 16,        gB + q * 4);
            CPA16(dB + (q + 16) * 16, gB + (q + 16) * 4);
        } else {
            int m  = tid >> 1;
            int qi = (tid & 1) * 2;
            long kb = (long)(k0 >> 8) * 65536 + (k0 & 255);
            const float* gA = Q  + (long)(m0 + m) * 256 + kb;
            const float* gB = Kp + (long)(n0 + m) * 256 + kb;
            unsigned dA = sA + ((buf * 128 + m) * P1) * 4;
            unsigned dB = sB + ((buf * 128 + m) * P1) * 4;
            CPA16(dA + qi * 16,       gA + qi * 4);
            CPA16(dA + (qi + 1) * 16, gA + (qi + 1) * 4);
            CPA16(dB + qi * 16,       gB + qi * 4);
            CPA16(dB + (qi + 1) * 16, gB + (qi + 1) * 4);
        }
    };

    float acc[16][4];
#pragma unroll
    for (int i = 0; i < 16; i++)
#pragma unroll
        for (int j = 0; j < 4; j++) acc[i][j] = 0.f;

    loadStage(0, kbeg);
    asm volatile("cp.async.commit_group;");
    int buf = 0;

    for (int k0 = kbeg; k0 < kend; k0 += 16) {
        int kn = k0 + 16;
        if (kn < kend) loadStage(buf ^ 1, kn);
        asm volatile("cp.async.commit_group;");
        asm volatile("cp.async.wait_group 1;");
        __syncthreads();

        const float* A_ = As + (L == 0 ? buf * 16 * P0 : buf * 128 * P1);
        const float* B_ = Bs + (L == 0 ? buf * 16 * P0 : buf * 128 * P1);
#pragma unroll
        for (int ks2 = 0; ks2 < 2; ks2++) {
            int kc = ks2 * 8 + c;
            unsigned a0[4], a1[4], a2[4], a3[4];
#pragma unroll
            for (int mt = 0; mt < 4; mt++) {
                int mr = wm * 64 + mt * 16 + r;
                if (L == 0) {
                    a0[mt] = __float_as_uint(A_[kc * P0 + mr]);
                    a1[mt] = __float_as_uint(A_[kc * P0 + mr + 8]);
                    a2[mt] = __float_as_uint(A_[(kc + 4) * P0 + mr]);
                    a3[mt] = __float_as_uint(A_[(kc + 4) * P0 + mr + 8]);
                } else {
                    a0[mt] = __float_as_uint(A_[mr * P1 + kc]);
                    a1[mt] = __float_as_uint(A_[(mr + 8) * P1 + kc]);
                    a2[mt] = __float_as_uint(A_[mr * P1 + kc + 4]);
                    a3[mt] = __float_as_uint(A_[(mr + 8) * P1 + kc + 4]);
                }
            }
#pragma unroll
            for (int j = 0; j < 4; j++) {
                int nn = wn * 32 + j * 8 + r;
                unsigned b0, b1;
                if (L == 0) {
                    b0 = __float_as_uint(B_[kc * P0 + nn]);
                    b1 = __float_as_uint(B_[(kc + 4) * P0 + nn]);
                } else {
                    b0 = __float_as_uint(B_[nn * P1 + kc]);
                    b1 = __float_as_uint(B_[nn * P1 + kc + 4]);
                }
#pragma unroll
                for (int mt = 0; mt < 4; mt++)
                    mma8(acc[mt * 4 + j], a0[mt], a1[mt], a2[mt], a3[mt], b0, b1);
            }
        }
        __syncthreads();
        buf ^= 1;
    }

#pragma unroll
    for (int mt = 0; mt < 4; mt++) {
#pragma unroll
        for (int j = 0; j < 4; j++) {
            int mrow = m0 + wm * 64 + mt * 16 + r;
            int n    = n0 + wn * 32 + j * 8 + c * 2;
            float* ci = acc[mt * 4 + j];
            atomicAdd(&C[(long)mrow * 256 + n],           ci[0]);
            atomicAdd(&C[(long)mrow * 256 + n + 1],       ci[1]);
            atomicAdd(&C[(long)(mrow + 8) * 256 + n],     ci[2]);
            atomicAdd(&C[(long)(mrow + 8) * 256 + n + 1], ci[3]);
        }
    }
}

// ---------------- unified cp.async tf32 GEMM: BM=MT*64, BN=64, BK=16, 128 threads -----
// C[m,n] = sum_k A[m*lda + k] * B[k*sbk + n]  (+bias[m], +res)
// A rows clamped to M-1 (results masked in epilogue). K = kit16*16 (A padded if needed).
template<int MT>
__global__ void __launch_bounds__(128, (MT == 1) ? 4 : 3) mma2_kernel(
    const float* __restrict__ A, const float* __restrict__ B, float* __restrict__ C,
    int M, int kit16, int lda, long sbk, int ldc, int zdiv,
    long sA1, long sA2, long sB1, long sB2, long sC1, long sC2,
    const float* __restrict__ bias,
    const float* __restrict__ res, long sR1, long sR2)
{
    constexpr int BM = MT * 64;
    constexpr int PA = 20;
    constexpr int PB = 68;
    __shared__ __align__(16) float As[2 * BM * PA];
    __shared__ __align__(16) float Bs[2 * 16 * PB];

    int z = blockIdx.z;
    int z1 = z / zdiv, z2 = z - z1 * zdiv;
    const float* Ap = A + (long)z1 * sA1 + (long)z2 * sA2;
    const float* Bp = B + (long)z1 * sB1 + (long)z2 * sB2;
    float*       Cp = C + (long)z1 * sC1 + (long)z2 * sC2;

    int m0 = blockIdx.x * BM;
    int n0 = blockIdx.y * 64;

    int tid = threadIdx.x, lane = tid & 31, warp = tid >> 5;
    int r = lane >> 2, c = lane & 3;

    unsigned sAu = (unsigned)__cvta_generic_to_shared(As);
    unsigned sBu = (unsigned)__cvta_generic_to_shared(Bs);

    auto loadStage = [&](int buf, int kit) {
        int k0 = kit * 16;
        // A: BM m x 16 k  (MT*2 chunks of 16B per thread)
#pragma unroll
        for (int i = 0; i < MT * 2; i++) {
            int q = tid + i * 128;
            int m = q >> 2, k4 = (q & 3) * 4;
            int gm = min(m0 + m, M - 1);
            CPA16(sAu + ((buf * BM + m) * PA + k4) * 4, Ap + (long)gm * lda + k0 + k4);
        }
        // B: 16 k x 64 n  (2 chunks per thread)
#pragma unroll
        for (int i = 0; i < 2; i++) {
            int q = tid + i * 128;
            int k = q >> 4, n4 = (q & 15) * 4;
            CPA16(sBu + ((buf * 16 + k) * PB + n4) * 4, Bp + (long)(k0 + k) * sbk + n0 + n4);
        }
    };

    float acc[MT * 8][4];
#pragma unroll
    for (int i = 0; i < MT * 8; i++)
#pragma unroll
        for (int j = 0; j < 4; j++) acc[i][j] = 0.f;

    loadStage(0, 0);
    asm volatile("cp.async.commit_group;");
    int buf = 0;

    for (int kit = 0; kit < kit16; kit++) {
        if (kit + 1 < kit16) loadStage(buf ^ 1, kit + 1);
        asm volatile("cp.async.commit_group;");
        asm volatile("cp.async.wait_group 1;");
        __syncthreads();

        const float* A_ = As + buf * BM * PA;
        const float* B_ = Bs + buf * 16 * PB;
#pragma unroll
        for (int ks2 = 0; ks2 < 2; ks2++) {
            int kc = ks2 * 8 + c;
            unsigned a0[MT], a1[MT], a2[MT], a3[MT];
#pragma unroll
            for (int mt = 0; mt < MT; mt++) {
                int mr = warp * (MT * 16) + mt * 16 + r;
                a0[mt] = __float_as_uint(A_[mr * PA + kc]);
                a1[mt] = __float_as_uint(A_[(mr + 8) * PA + kc]);
                a2[mt] = __float_as_uint(A_[mr * PA + kc + 4]);
                a3[mt] = __float_as_uint(A_[(mr + 8) * PA + kc + 4]);
            }
#pragma unroll
            for (int j = 0; j < 8; j++) {
                int nn = j * 8 + r;
                unsigned b0 = __float_as_uint(B_[kc * PB + nn]);
                unsigned b1 = __float_as_uint(B_[(kc + 4) * PB + nn]);
#pragma unroll
                for (int mt = 0; mt < MT; mt++)
                    mma8(acc[mt * 8 + j], a0[mt], a1[mt], a2[mt], a3[mt], b0, b1);
            }
        }
        __syncthreads();
        buf ^= 1;
    }

    const float* Rp = res ? res + (long)z1 * sR1 + (long)z2 * sR2 : nullptr;
#pragma unroll
    for (int mt = 0; mt < MT; mt++) {
#pragma unroll
        for (int j = 0; j < 8; j++) {
            int mA = m0 + warp * (MT * 16) + mt * 16 + r;
            int n  = n0 + j * 8 + c * 2;
            float* ci = acc[mt * 8 + j];
#pragma unroll
            for (int half = 0; half < 2; half++) {
                int mrow = mA + half * 8;
                if (mrow >= M) continue;
                float bv = bias ? bias[mrow] : 0.f;
                float v0 = ci[half * 2 + 0] + bv;
                float v1 = ci[half * 2 + 1] + bv;
                long off = (long)mrow * ldc + n;
                if (Rp) { v0 += Rp[off]; v1 += Rp[off + 1]; }
                *reinterpret_cast<float2*>(&Cp[off]) = make_float2(v0, v1);
            }
        }
    }
}

extern "C" void kernel_launch(void* const* d_in, const int* in_sizes, int n_in,
                              void* d_out, int out_size)
{
    const float* x        = (const float*)d_in[0];
    const float* w_ln_w   = (const float*)d_in[2];
    const float* w_ln_b   = (const float*)d_in[3];
    const float* w_qkv_w  = (const float*)d_in[4];
    const float* w_qkv_b  = (const float*)d_in[5];
    const float* w_dw_w   = (const float*)d_in[6];
    const float* w_dw_b   = (const float*)d_in[7];
    const float* w_proj_w = (const float*)d_in[8];
    const float* w_proj_b = (const float*)d_in[9];
    const float* w_temp   = (const float*)d_in[10];
    const float* h_ln_w   = (const float*)d_in[11];
    const float* h_ln_b   = (const float*)d_in[12];
    const float* h_qkv_w  = (const float*)d_in[13];
    const float* h_qkv_b  = (const float*)d_in[14];
    const float* h_dw_w   = (const float*)d_in[15];
    const float* h_dw_b   = (const float*)d_in[16];
    const float* h_proj_w = (const float*)d_in[17];
    const float* h_proj_b = (const float*)d_in[18];
    const float* h_temp   = (const float*)d_in[19];
    const float* n2_w     = (const float*)d_in[20];
    const float* n2_b     = (const float*)d_in[21];
    const float* ffn_in_w = (const float*)d_in[22];
    const float* ffn_in_b = (const float*)d_in[23];
    const float* ffn_dw_w = (const float*)d_in[24];
    const float* ffn_dw_b = (const float*)d_in[25];
    const float* ffn_out_w= (const float*)d_in[26];
    const float* ffn_out_b= (const float*)d_in[27];
    float* out = (float*)d_out;

    float *bufA, *bufM, *bufZ, *qkv1, *qkv2, *attn, *sq, *sk, *wpad;
    cudaGetSymbolAddress((void**)&bufA, g_bufA);
    cudaGetSymbolAddress((void**)&bufM, g_bufM);
    cudaGetSymbolAddress((void**)&bufZ, g_bufZ);
    cudaGetSymbolAddress((void**)&qkv1, g_qkv1);
    cudaGetSymbolAddress((void**)&qkv2, g_qkv2);
    cudaGetSymbolAddress((void**)&attn, g_attn);
    cudaGetSymbolAddress((void**)&sq,   g_sq);
    cudaGetSymbolAddress((void**)&sk,   g_sk);
    cudaGetSymbolAddress((void**)&wpad, g_wpad);

    const long sX = (long)CDIM * HWD;
    const long sQ = (long)3 * CDIM * HWD;
    const int KS = 32;

    padw_kernel<<<(64 * 176 + 255) / 256, 256>>>(ffn_out_w, wpad);

    // ================= attention (WxW) =================
    ln_kernel<<<(BATCH * HWD) / 256, 256>>>(x, w_ln_w, w_ln_b, bufA);
    // qkv = W[192,64] @ ln : MT=1, grid (3, 1024, 4) — no wasted rows
    mma2_kernel<1><<<dim3(3, 1024, BATCH), 128>>>(w_qkv_w, bufA, qkv1,
        192, 4, 64, HWD, HWD, 1, 0,0, sX,0, sQ,0, w_qkv_b, nullptr, 0,0);
    dwconv_rows_kernel<<<BATCH*192*64, 256>>>(qkv1, w_dw_w, w_dw_b, qkv2, 192, 128);
    cudaMemsetAsync(attn, 0, (size_t)BATCH * WW * WW * sizeof(float));
    gram_kernel<0><<<dim3(2, 2, BATCH * KS), 256>>>(qkv2, qkv2 + 64*(long)HWD, attn, KS);
    softmax_kernel<<<dim3(WW, BATCH), 256>>>(attn, w_temp, nullptr, nullptr);
    // AV: v[16384,256] @ attn[256,256]
    mma2_kernel<2><<<dim3(128, 4, BATCH), 128>>>(qkv2 + 128*(long)HWD, attn, bufA,
        CHROWS, 16, 256, 256, 256, 1, sQ,0, (long)WW*WW,0, sX,0, nullptr, nullptr, 0,0);
    // proj + residual x -> bufM
    mma2_kernel<1><<<dim3(1, 1024, BATCH), 128>>>(w_proj_w, bufA, bufM,
        64, 4, 64, HWD, HWD, 1, 0,0, sX,0, sX,0, w_proj_b, x, sX,0);

    // ================= attention (HxH) =================
    ln_kernel<<<(BATCH * HWD) / 256, 256>>>(bufM, h_ln_w, h_ln_b, bufA);
    mma2_kernel<1><<<dim3(3, 1024, BATCH), 128>>>(h_qkv_w, bufA, qkv1,
        192, 4, 64, HWD, HWD, 1, 0,0, sX,0, sQ,0, h_qkv_b, nullptr, 0,0);
    dwconv_rows_kernel<<<BATCH*192*64, 256>>>(qkv1, h_dw_w, h_dw_b, qkv2, 192, 0);
    hnorm_kernel<<<dim3(HH, BATCH), 256>>>(qkv2,                sq);
    hnorm_kernel<<<dim3(HH, BATCH), 256>>>(qkv2 + 64*(long)HWD, sk);
    cudaMemsetAsync(attn, 0, (size_t)BATCH * WW * WW * sizeof(float));
    gram_kernel<1><<<dim3(2, 2, BATCH * KS), 256>>>(qkv2, qkv2 + 64*(long)HWD, attn, KS);
    softmax_kernel<<<dim3(WW, BATCH), 256>>>(attn, h_temp, sq, sk);
    // AV: per (b,c): attn[256,256] @ v[c][256,256]
    mma2_kernel<2><<<dim3(2, 4, BATCH * 64), 128>>>(attn, qkv2 + 128*(long)HWD, bufA,
        256, 16, 256, 256, 256, 64, (long)WW*WW,0, sQ,(long)HWD, sX,(long)HWD,
        nullptr, nullptr, 0,0);
    // proj + residual m -> bufZ
    mma2_kernel<1><<<dim3(1, 1024, BATCH), 128>>>(h_proj_w, bufA, bufZ,
        64, 4, 64, HWD, HWD, 1, 0,0, sX,0, sX,0, h_proj_b, bufM, sX,0);

    // ================= FFN =================
    ln_kernel<<<(BATCH * HWD) / 256, 256>>>(bufZ, n2_w, n2_b, bufA);
    mma2_kernel<2><<<dim3(3, 1024, BATCH), 128>>>(ffn_in_w, bufA, qkv1,
        HID2, 4, 64, HWD, HWD, 1, 0,0, sX,0, (long)HID2*HWD,0, ffn_in_b, nullptr, 0,0);
    dwconv_gate_kernel<<<((long)BATCH*HID*HWD/4 + 255)/256, 256>>>(qkv1, ffn_dw_w, ffn_dw_b, qkv2);
    // out = Wout(padded)[64,176] @ gated[170(176),HWD] + bias + z
    mma2_kernel<1><<<dim3(1, 1024, BATCH), 128>>>(wpad, qkv2, out,
        64, 11, 176, HWD, HWD, 1, 0,0, (long)HID*HWD,0, sX,0, ffn_out_b, bufZ, sX,0);
}

// round 7
// speedup vs baseline: 2.8639x; 1.0342x over previous
#include <cuda_runtime.h>
#include <math.h>

#define BATCH 4
#define CDIM  64
#define HH    256
#define WW    256
#define HWD   65536          // H*W
#define CHROWS 16384         // C*H
#define HID   170
#define HID2  340

// ---------------- scratch (device globals; no allocations allowed) ----------------
__device__ float g_bufA[(size_t)BATCH * CDIM * HWD];
__device__ float g_bufM[(size_t)BATCH * CDIM * HWD];
__device__ float g_bufZ[(size_t)BATCH * CDIM * HWD];
__device__ float g_qkv1[(size_t)BATCH * HID2 * HWD];
__device__ float g_qkv2[(size_t)BATCH * HID2 * HWD];
__device__ float g_attn[(size_t)BATCH * WW * WW];
__device__ float g_sq[BATCH * HH];
__device__ float g_sk[BATCH * HH];
__device__ float g_wpad[64 * 176];

// ---------------- helpers ----------------
__device__ __forceinline__ void mma8(float* d, unsigned a0, unsigned a1, unsigned a2, unsigned a3,
                                     unsigned b0, unsigned b1) {
    asm volatile(
        "mma.sync.aligned.m16n8k8.row.col.f32.tf32.tf32.f32 "
        "{%0,%1,%2,%3},{%4,%5,%6,%7},{%8,%9},{%0,%1,%2,%3};\n"
        : "+f"(d[0]), "+f"(d[1]), "+f"(d[2]), "+f"(d[3])
        : "r"(a0), "r"(a1), "r"(a2), "r"(a3), "r"(b0), "r"(b1));
}
#define CPA16(dst_u32, src_ptr) \
    asm volatile("cp.async.cg.shared.global [%0], [%1], 16;" :: "r"(dst_u32), "l"(src_ptr))

// ---------------- LayerNorm over channel dim (per pixel) ----------------
__global__ void ln_kernel(const float* __restrict__ x, const float* __restrict__ w,
                          const float* __restrict__ b, float* __restrict__ y)
{
    long p = (long)blockIdx.x * blockDim.x + threadIdx.x;
    if (p >= (long)BATCH * HWD) return;
    int bb  = (int)(p >> 16);
    int pix = (int)(p & (HWD - 1));
    const float* xp = x + (long)bb * CDIM * HWD + pix;
    float s = 0.f, s2 = 0.f;
#pragma unroll
    for (int c = 0; c < CDIM; c++) {
        float v = xp[(long)c * HWD];
        s += v; s2 += v * v;
    }
    float mu  = s * (1.0f / CDIM);
    float var = s2 * (1.0f / CDIM) - mu * mu;
    float inv = rsqrtf(var + 1e-5f);
    float* yp = y + (long)bb * CDIM * HWD + pix;
#pragma unroll
    for (int c = 0; c < CDIM; c++) {
        float v = xp[(long)c * HWD];
        yp[(long)c * HWD] = (v - mu) * inv * w[c] + b[c];
    }
}

// ---------------- pad ffn_out weight 64x170 -> 64x176 (zero fill) ----------------
__global__ void padw_kernel(const float* __restrict__ w, float* __restrict__ wp)
{
    int i = blockIdx.x * 256 + threadIdx.x;
    if (i >= 64 * 176) return;
    int r = i / 176, c = i - r * 176;
    wp[i] = (c < 170) ? w[r * 170 + c] : 0.f;
}

// ---------------- depthwise 3x3, warp-per-row, shuffle halos ----------------
// block = 256 thr = 8 warps = 8 consecutive h-rows of one (b,c); lane owns 8 px.
// If c < normCh, the output row is divided by max(||row||, 1e-12).
__global__ void dwconv_rows_kernel(const float* __restrict__ x, const float* __restrict__ wt,
                                   const float* __restrict__ bias, float* __restrict__ y,
                                   int OC, int normCh)
{
    long bidx = blockIdx.x;
    int hb = (int)(bidx & 31) * 8;
    long bc = bidx >> 5;
    int c = (int)(bc % OC);
    int warp = threadIdx.x >> 5, lane = threadIdx.x & 31;
    int h = hb + warp;
    const float* xp = x + (bc << 16);
    float b0 = bias[c];
    float acc[8];
#pragma unroll
    for (int j = 0; j < 8; j++) acc[j] = b0;
    const float* wc = wt + c * 9;
#pragma unroll
    for (int kh = -1; kh <= 1; kh++) {
        int hh = h + kh;
        if (hh < 0 || hh >= HH) continue;
        const float4* row = reinterpret_cast<const float4*>(xp + hh * WW);
        float4 a  = row[lane * 2];
        float4 b4 = row[lane * 2 + 1];
        float vm1 = __shfl_up_sync(0xffffffffu, b4.w, 1);
        if (lane == 0) vm1 = 0.f;
        float vp8 = __shfl_down_sync(0xffffffffu, a.x, 1);
        if (lane == 31) vp8 = 0.f;
        float vals[10] = {vm1, a.x, a.y, a.z, a.w, b4.x, b4.y, b4.z, b4.w, vp8};
        const float* wr = wc + (kh + 1) * 3;
#pragma unroll
        for (int kw = 0; kw < 3; kw++) {
            float g = wr[kw];
#pragma unroll
            for (int j = 0; j < 8; j++)
                acc[j] = fmaf(g, vals[j + kw], acc[j]);
        }
    }
    if (c < normCh) {
        float s = 0.f;
#pragma unroll
        for (int j = 0; j < 8; j++) s += acc[j] * acc[j];
#pragma unroll
        for (int o = 16; o > 0; o >>= 1) s += __shfl_xor_sync(0xffffffffu, s, o);
        float inv = 1.f / fmaxf(sqrtf(s), 1e-12f);
#pragma unroll
        for (int j = 0; j < 8; j++) acc[j] *= inv;
    }
    float4* yo = reinterpret_cast<float4*>(y + (bc << 16) + h * WW);
    yo[lane * 2]     = make_float4(acc[0], acc[1], acc[2], acc[3]);
    yo[lane * 2 + 1] = make_float4(acc[4], acc[5], acc[6], acc[7]);
}

// ---------------- fused FFN depthwise 3x3 + GELU gate, warp-per-row ----------------
__global__ void dwconv_gate_kernel(const float* __restrict__ x, const float* __restrict__ wt,
                                   const float* __restrict__ bias, float* __restrict__ g)
{
    long bidx = blockIdx.x;
    int hb = (int)(bidx & 31) * 8;
    long bc = bidx >> 5;            // b*HID + c
    int c = (int)(bc % HID);
    int b = (int)(bc / HID);
    int warp = threadIdx.x >> 5, lane = threadIdx.x & 31;
    int h = hb + warp;
    const float* xp1 = x + ((long)b * HID2 + c) * HWD;
    const float* xp2 = xp1 + (long)HID * HWD;
    float bb1 = bias[c], bb2 = bias[c + HID];
    float acc1[8], acc2[8];
#pragma unroll
    for (int j = 0; j < 8; j++) { acc1[j] = bb1; acc2[j] = bb2; }
    const float* w1 = wt + c * 9;
    const float* w2 = wt + (c + HID) * 9;
#pragma unroll
    for (int kh = -1; kh <= 1; kh++) {
        int hh = h + kh;
        if (hh < 0 || hh >= HH) continue;
        {
            const float4* row = reinterpret_cast<const float4*>(xp1 + hh * WW);
            float4 a  = row[lane * 2];
            float4 b4 = row[lane * 2 + 1];
            float vm1 = __shfl_up_sync(0xffffffffu, b4.w, 1);
            if (lane == 0) vm1 = 0.f;
            float vp8 = __shfl_down_sync(0xffffffffu, a.x, 1);
            if (lane == 31) vp8 = 0.f;
            float vals[10] = {vm1, a.x, a.y, a.z, a.w, b4.x, b4.y, b4.z, b4.w, vp8};
            const float* wr = w1 + (kh + 1) * 3;
#pragma unroll
            for (int kw = 0; kw < 3; kw++) {
                float gg = wr[kw];
#pragma unroll
                for (int j = 0; j < 8; j++)
                    acc1[j] = fmaf(gg, vals[j + kw], acc1[j]);
            }
        }
        {
            const float4* row = reinterpret_cast<const float4*>(xp2 + hh * WW);
            float4 a  = row[lane * 2];
            float4 b4 = row[lane * 2 + 1];
            float vm1 = __shfl_up_sync(0xffffffffu, b4.w, 1);
            if (lane == 0) vm1 = 0.f;
            float vp8 = __shfl_down_sync(0xffffffffu, a.x, 1);
            if (lane == 31) vp8 = 0.f;
            float vals[10] = {vm1, a.x, a.y, a.z, a.w, b4.x, b4.y, b4.z, b4.w, vp8};
            const float* wr = w2 + (kh + 1) * 3;
#pragma unroll
            for (int kw = 0; kw < 3; kw++) {
                float gg = wr[kw];
#pragma unroll
                for (int j = 0; j < 8; j++)
                    acc2[j] = fmaf(gg, vals[j + kw], acc2[j]);
            }
        }
    }
    const float kk = 0.70710678118654752f;
    float o[8];
#pragma unroll
    for (int j = 0; j < 8; j++)
        o[j] = 0.5f * acc1[j] * (1.0f + erff(acc1[j] * kk)) * acc2[j];
    float4* go = reinterpret_cast<float4*>(g + ((long)b * HID + c) * HWD + h * WW);
    go[lane * 2]     = make_float4(o[0], o[1], o[2], o[3]);
    go[lane * 2 + 1] = make_float4(o[4], o[5], o[6], o[7]);
}

// ---------------- hxh inverse norm: per (b,h) over (c,w) ----------------
__global__ void hnorm_kernel(const float* __restrict__ src, float* __restrict__ out)
{
    int b = blockIdx.y, h = blockIdx.x;
    int t = threadIdx.x;
    const float* p = src + (long)b * (3 * CDIM) * HWD + (long)h * WW + t;
    float s = 0.f;
#pragma unroll
    for (int c = 0; c < CDIM; c++) { float v = p[(long)c * HWD]; s += v * v; }
    __shared__ float red[256];
    red[t] = s; __syncthreads();
    for (int o = 128; o > 0; o >>= 1) { if (t < o) red[t] += red[t + o]; __syncthreads(); }
    if (t == 0) out[b * HH + h] = 1.f / fmaxf(sqrtf(red[0]), 1e-12f);
}

// ---------------- softmax over last dim of [B, 256, 256] ----------------
__global__ void softmax_kernel(float* __restrict__ attn, const float* __restrict__ temp,
                               const float* __restrict__ sq, const float* __restrict__ sk)
{
    int b = blockIdx.y;
    int r = blockIdx.x;
    float* row = attn + ((long)b * WW + r) * WW;
    int t = threadIdx.x;
    float v = row[t] * temp[0];
    if (sq) v *= sq[b * WW + r] * sk[b * WW + t];
    __shared__ float red[256];
    red[t] = v; __syncthreads();
    for (int o = 128; o > 0; o >>= 1) { if (t < o) red[t] = fmaxf(red[t], red[t + o]); __syncthreads(); }
    float mx = red[0]; __syncthreads();
    float e = __expf(v - mx);
    red[t] = e; __syncthreads();
    for (int o = 128; o > 0; o >>= 1) { if (t < o) red[t] += red[t + o]; __syncthreads(); }
    row[t] = e * (1.f / red[0]);
}

// ---------------- dedicated gram kernel (unchanged) ----------------
template<int L>
__global__ void __launch_bounds__(256, 2) gram_kernel(
    const float* __restrict__ Qb, const float* __restrict__ Kb,
    float* __restrict__ Cb, int KS)
{
    constexpr int P0 = 136;
    constexpr int P1 = 20;
    constexpr int SSZ = (L == 0) ? 2 * 16 * P0 : 2 * 128 * P1;
    __shared__ __align__(16) float As[SSZ];
    __shared__ __align__(16) float Bs[SSZ];

    int z = blockIdx.z;
    int b = z / KS, ks = z - b * KS;
    const float* Q = Qb + (long)b * (3 * CDIM * HWD);
    const float* Kp = Kb + (long)b * (3 * CDIM * HWD);
    float* C = Cb + (long)b * 65536;
    int m0 = blockIdx.x * 128, n0 = blockIdx.y * 128;
    int kchunk = 16384 / KS;
    int kbeg = ks * kchunk, kend = kbeg + kchunk;

    int tid = threadIdx.x, lane = tid & 31, warp = tid >> 5;
    int wm = warp & 1, wn = warp >> 1;
    int r = lane >> 2, c = lane & 3;

    unsigned sA = (unsigned)__cvta_generic_to_shared(As);
    unsigned sB = (unsigned)__cvta_generic_to_shared(Bs);

    auto loadStage = [&](int buf, int k0) {
        if (L == 0) {
            int row = tid >> 4;
            int q   = tid & 15;
            const float* gA = Q  + (long)(k0 + row) * 256 + m0;
            const float* gB = Kp + (long)(k0 + row) * 256 + n0;
            unsigned dA = sA + ((buf * 16 + row) * P0) * 4;
            unsigned dB = sB + ((buf * 16 + row) * P0) * 4;
            CPA16(dA + q * 16,        gA + q * 4);
            CPA16(dA + (q + 16) * 16, gA + (q + 16) * 4);
            CPA16(dB + q * 16,        gB + q * 4);
            CPA16(dB + (q + 16) * 16, gB + (q + 16) * 4);
        } else {
            int m  = tid >> 1;
            int qi = (tid & 1) * 2;
            long kb = (long)(k0 >> 8) * 65536 + (k0 & 255);
            const float* gA = Q  + (long)(m0 + m) * 256 + kb;
            const float* gB = Kp + (long)(n0 + m) * 256 + kb;
            unsigned dA = sA + ((buf * 128 + m) * P1) * 4;
            unsigned dB = sB + ((buf * 128 + m) * P1) * 4;
            CPA16(dA + qi * 16,       gA + qi * 4);
            CPA16(dA + (qi + 1) * 16, gA + (qi + 1) * 4);
            CPA16(dB + qi * 16,       gB + qi * 4);
            CPA16(dB + (qi + 1) * 16, gB + (qi + 1) * 4);
        }
    };

    float acc[16][4];
#pragma unroll
    for (int i = 0; i < 16; i++)
#pragma unroll
        for (int j = 0; j < 4; j++) acc[i][j] = 0.f;

    loadStage(0, kbeg);
    asm volatile("cp.async.commit_group;");
    int buf = 0;

    for (int k0 = kbeg; k0 < kend; k0 += 16) {
        int kn = k0 + 16;
        if (kn < kend) loadStage(buf ^ 1, kn);
        asm volatile("cp.async.commit_group;");
        asm volatile("cp.async.wait_group 1;");
        __syncthreads();

        const float* A_ = As + (L == 0 ? buf * 16 * P0 : buf * 128 * P1);
        const float* B_ = Bs + (L == 0 ? buf * 16 * P0 : buf * 128 * P1);
#pragma unroll
        for (int ks2 = 0; ks2 < 2; ks2++) {
            int kc = ks2 * 8 + c;
            unsigned a0[4], a1[4], a2[4], a3[4];
#pragma unroll
            for (int mt = 0; mt < 4; mt++) {
                int mr = wm * 64 + mt * 16 + r;
                if (L == 0) {
                    a0[mt] = __float_as_uint(A_[kc * P0 + mr]);
                    a1[mt] = __float_as_uint(A_[kc * P0 + mr + 8]);
                    a2[mt] = __float_as_uint(A_[(kc + 4) * P0 + mr]);
                    a3[mt] = __float_as_uint(A_[(kc + 4) * P0 + mr + 8]);
                } else {
                    a0[mt] = __float_as_uint(A_[mr * P1 + kc]);
                    a1[mt] = __float_as_uint(A_[(mr + 8) * P1 + kc]);
                    a2[mt] = __float_as_uint(A_[mr * P1 + kc + 4]);
                    a3[mt] = __float_as_uint(A_[(mr + 8) * P1 + kc + 4]);
                }
            }
#pragma unroll
            for (int j = 0; j < 4; j++) {
                int nn = wn * 32 + j * 8 + r;
                unsigned b0, b1;
                if (L == 0) {
                    b0 = __float_as_uint(B_[kc * P0 + nn]);
                    b1 = __float_as_uint(B_[(kc + 4) * P0 + nn]);
                } else {
                    b0 = __float_as_uint(B_[nn * P1 + kc]);
                    b1 = __float_as_uint(B_[nn * P1 + kc + 4]);
                }
#pragma unroll
                for (int mt = 0; mt < 4; mt++)
                    mma8(acc[mt * 4 + j], a0[mt], a1[mt], a2[mt], a3[mt], b0, b1);
            }
        }
        __syncthreads();
        buf ^= 1;
    }

#pragma unroll
    for (int mt = 0; mt < 4; mt++) {
#pragma unroll
        for (int j = 0; j < 4; j++) {
            int mrow = m0 + wm * 64 + mt * 16 + r;
            int n    = n0 + wn * 32 + j * 8 + c * 2;
            float* ci = acc[mt * 4 + j];
            atomicAdd(&C[(long)mrow * 256 + n],           ci[0]);
            atomicAdd(&C[(long)mrow * 256 + n + 1],       ci[1]);
            atomicAdd(&C[(long)(mrow + 8) * 256 + n],     ci[2]);
            atomicAdd(&C[(long)(mrow + 8) * 256 + n + 1], ci[3]);
        }
    }
}

// ---------------- unified cp.async tf32 GEMM: BM=MT*64, BN=64, BK=16, 128 threads -----
template<int MT>
__global__ void __launch_bounds__(128, (MT == 1) ? 4 : 3) mma2_kernel(
    const float* __restrict__ A, const float* __restrict__ B, float* __restrict__ C,
    int M, int kit16, int lda, long sbk, int ldc, int zdiv,
    long sA1, long sA2, long sB1, long sB2, long sC1, long sC2,
    const float* __restrict__ bias,
    const float* __restrict__ res, long sR1, long sR2)
{
    constexpr int BM = MT * 64;
    constexpr int PA = 20;
    constexpr int PB = 68;
    __shared__ __align__(16) float As[2 * BM * PA];
    __shared__ __align__(16) float Bs[2 * 16 * PB];

    int z = blockIdx.z;
    int z1 = z / zdiv, z2 = z - z1 * zdiv;
    const float* Ap = A + (long)z1 * sA1 + (long)z2 * sA2;
    const float* Bp = B + (long)z1 * sB1 + (long)z2 * sB2;
    float*       Cp = C + (long)z1 * sC1 + (long)z2 * sC2;

    int m0 = blockIdx.x * BM;
    int n0 = blockIdx.y * 64;

    int tid = threadIdx.x, lane = tid & 31, warp = tid >> 5;
    int r = lane >> 2, c = lane & 3;

    unsigned sAu = (unsigned)__cvta_generic_to_shared(As);
    unsigned sBu = (unsigned)__cvta_generic_to_shared(Bs);

    auto loadStage = [&](int buf, int kit) {
        int k0 = kit * 16;
#pragma unroll
        for (int i = 0; i < MT * 2; i++) {
            int q = tid + i * 128;
            int m = q >> 2, k4 = (q & 3) * 4;
            int gm = min(m0 + m, M - 1);
            CPA16(sAu + ((buf * BM + m) * PA + k4) * 4, Ap + (long)gm * lda + k0 + k4);
        }
#pragma unroll
        for (int i = 0; i < 2; i++) {
            int q = tid + i * 128;
            int k = q >> 4, n4 = (q & 15) * 4;
            CPA16(sBu + ((buf * 16 + k) * PB + n4) * 4, Bp + (long)(k0 + k) * sbk + n0 + n4);
        }
    };

    float acc[MT * 8][4];
#pragma unroll
    for (int i = 0; i < MT * 8; i++)
#pragma unroll
        for (int j = 0; j < 4; j++) acc[i][j] = 0.f;

    loadStage(0, 0);
    asm volatile("cp.async.commit_group;");
    int buf = 0;

    for (int kit = 0; kit < kit16; kit++) {
        if (kit + 1 < kit16) loadStage(buf ^ 1, kit + 1);
        asm volatile("cp.async.commit_group;");
        asm volatile("cp.async.wait_group 1;");
        __syncthreads();

        const float* A_ = As + buf * BM * PA;
        const float* B_ = Bs + buf * 16 * PB;
#pragma unroll
        for (int ks2 = 0; ks2 < 2; ks2++) {
            int kc = ks2 * 8 + c;
            unsigned a0[MT], a1[MT], a2[MT], a3[MT];
#pragma unroll
            for (int mt = 0; mt < MT; mt++) {
                int mr = warp * (MT * 16) + mt * 16 + r;
                a0[mt] = __float_as_uint(A_[mr * PA + kc]);
                a1[mt] = __float_as_uint(A_[(mr + 8) * PA + kc]);
                a2[mt] = __float_as_uint(A_[mr * PA + kc + 4]);
                a3[mt] = __float_as_uint(A_[(mr + 8) * PA + kc + 4]);
            }
#pragma unroll
            for (int j = 0; j < 8; j++) {
                int nn = j * 8 + r;
                unsigned b0 = __float_as_uint(B_[kc * PB + nn]);
                unsigned b1 = __float_as_uint(B_[(kc + 4) * PB + nn]);
#pragma unroll
                for (int mt = 0; mt < MT; mt++)
                    mma8(acc[mt * 8 + j], a0[mt], a1[mt], a2[mt], a3[mt], b0, b1);
            }
        }
        __syncthreads();
        buf ^= 1;
    }

    const float* Rp = res ? res + (long)z1 * sR1 + (long)z2 * sR2 : nullptr;
#pragma unroll
    for (int mt = 0; mt < MT; mt++) {
#pragma unroll
        for (int j = 0; j < 8; j++) {
            int mA = m0 + warp * (MT * 16) + mt * 16 + r;
            int n  = n0 + j * 8 + c * 2;
            float* ci = acc[mt * 8 + j];
#pragma unroll
            for (int half = 0; half < 2; half++) {
                int mrow = mA + half * 8;
                if (mrow >= M) continue;
                float bv = bias ? bias[mrow] : 0.f;
                float v0 = ci[half * 2 + 0] + bv;
                float v1 = ci[half * 2 + 1] + bv;
                long off = (long)mrow * ldc + n;
                if (Rp) { v0 += Rp[off]; v1 += Rp[off + 1]; }
                *reinterpret_cast<float2*>(&Cp[off]) = make_float2(v0, v1);
            }
        }
    }
}

extern "C" void kernel_launch(void* const* d_in, const int* in_sizes, int n_in,
                              void* d_out, int out_size)
{
    const float* x        = (const float*)d_in[0];
    const float* w_ln_w   = (const float*)d_in[2];
    const float* w_ln_b   = (const float*)d_in[3];
    const float* w_qkv_w  = (const float*)d_in[4];
    const float* w_qkv_b  = (const float*)d_in[5];
    const float* w_dw_w   = (const float*)d_in[6];
    const float* w_dw_b   = (const float*)d_in[7];
    const float* w_proj_w = (const float*)d_in[8];
    const float* w_proj_b = (const float*)d_in[9];
    const float* w_temp   = (const float*)d_in[10];
    const float* h_ln_w   = (const float*)d_in[11];
    const float* h_ln_b   = (const float*)d_in[12];
    const float* h_qkv_w  = (const float*)d_in[13];
    const float* h_qkv_b  = (const float*)d_in[14];
    const float* h_dw_w   = (const float*)d_in[15];
    const float* h_dw_b   = (const float*)d_in[16];
    const float* h_proj_w = (const float*)d_in[17];
    const float* h_proj_b = (const float*)d_in[18];
    const float* h_temp   = (const float*)d_in[19];
    const float* n2_w     = (const float*)d_in[20];
    const float* n2_b     = (const float*)d_in[21];
    const float* ffn_in_w = (const float*)d_in[22];
    const float* ffn_in_b = (const float*)d_in[23];
    const float* ffn_dw_w = (const float*)d_in[24];
    const float* ffn_dw_b = (const float*)d_in[25];
    const float* ffn_out_w= (const float*)d_in[26];
    const float* ffn_out_b= (const float*)d_in[27];
    float* out = (float*)d_out;

    float *bufA, *bufM, *bufZ, *qkv1, *qkv2, *attn, *sq, *sk, *wpad;
    cudaGetSymbolAddress((void**)&bufA, g_bufA);
    cudaGetSymbolAddress((void**)&bufM, g_bufM);
    cudaGetSymbolAddress((void**)&bufZ, g_bufZ);
    cudaGetSymbolAddress((void**)&qkv1, g_qkv1);
    cudaGetSymbolAddress((void**)&qkv2, g_qkv2);
    cudaGetSymbolAddress((void**)&attn, g_attn);
    cudaGetSymbolAddress((void**)&sq,   g_sq);
    cudaGetSymbolAddress((void**)&sk,   g_sk);
    cudaGetSymbolAddress((void**)&wpad, g_wpad);

    const long sX = (long)CDIM * HWD;
    const long sQ = (long)3 * CDIM * HWD;
    const int KS = 32;

    padw_kernel<<<(64 * 176 + 255) / 256, 256>>>(ffn_out_w, wpad);

    // ================= attention (WxW) =================
    ln_kernel<<<(BATCH * HWD) / 256, 256>>>(x, w_ln_w, w_ln_b, bufA);
    mma2_kernel<1><<<dim3(3, 1024, BATCH), 128>>>(w_qkv_w, bufA, qkv1,
        192, 4, 64, HWD, HWD, 1, 0,0, sX,0, sQ,0, w_qkv_b, nullptr, 0,0);
    dwconv_rows_kernel<<<BATCH*192*32, 256>>>(qkv1, w_dw_w, w_dw_b, qkv2, 192, 128);
    cudaMemsetAsync(attn, 0, (size_t)BATCH * WW * WW * sizeof(float));
    gram_kernel<0><<<dim3(2, 2, BATCH * KS), 256>>>(qkv2, qkv2 + 64*(long)HWD, attn, KS);
    softmax_kernel<<<dim3(WW, BATCH), 256>>>(attn, w_temp, nullptr, nullptr);
    mma2_kernel<2><<<dim3(128, 4, BATCH), 128>>>(qkv2 + 128*(long)HWD, attn, bufA,
        CHROWS, 16, 256, 256, 256, 1, sQ,0, (long)WW*WW,0, sX,0, nullptr, nullptr, 0,0);
    mma2_kernel<1><<<dim3(1, 1024, BATCH), 128>>>(w_proj_w, bufA, bufM,
        64, 4, 64, HWD, HWD, 1, 0,0, sX,0, sX,0, w_proj_b, x, sX,0);

    // ================= attention (HxH) =================
    ln_kernel<<<(BATCH * HWD) / 256, 256>>>(bufM, h_ln_w, h_ln_b, bufA);
    mma2_kernel<1><<<dim3(3, 1024, BATCH), 128>>>(h_qkv_w, bufA, qkv1,
        192, 4, 64, HWD, HWD, 1, 0,0, sX,0, sQ,0, h_qkv_b, nullptr, 0,0);
    dwconv_rows_kernel<<<BATCH*192*32, 256>>>(qkv1, h_dw_w, h_dw_b, qkv2, 192, 0);
    hnorm_kernel<<<dim3(HH, BATCH), 256>>>(qkv2,                sq);
    hnorm_kernel<<<dim3(HH, BATCH), 256>>>(qkv2 + 64*(long)HWD, sk);
    cudaMemsetAsync(attn, 0, (size_t)BATCH * WW * WW * sizeof(float));
    gram_kernel<1><<<dim3(2, 2, BATCH * KS), 256>>>(qkv2, qkv2 + 64*(long)HWD, attn, KS);
    softmax_kernel<<<dim3(WW, BATCH), 256>>>(attn, h_temp, sq, sk);
    mma2_kernel<2><<<dim3(2, 4, BATCH * 64), 128>>>(attn, qkv2 + 128*(long)HWD, bufA,
        256, 16, 256, 256, 256, 64, (long)WW*WW,0, sQ,(long)HWD, sX,(long)HWD,
        nullptr, nullptr, 0,0);
    mma2_kernel<1><<<dim3(1, 1024, BATCH), 128>>>(h_proj_w, bufA, bufZ,
        64, 4, 64, HWD, HWD, 1, 0,0, sX,0, sX,0, h_proj_b, bufM, sX,0);

    // ================= FFN =================
    ln_kernel<<<(BATCH * HWD) / 256, 256>>>(bufZ, n2_w, n2_b, bufA);
    mma2_kernel<2><<<dim3(3, 1024, BATCH), 128>>>(ffn_in_w, bufA, qkv1,
        HID2, 4, 64, HWD, HWD, 1, 0,0, sX,0, (long)HID2*HWD,0, ffn_in_b, nullptr, 0,0);
    dwconv_gate_kernel<<<BATCH*HID*32, 256>>>(qkv1, ffn_dw_w, ffn_dw_b, qkv2);
    mma2_kernel<1><<<dim3(1, 1024, BATCH), 128>>>(wpad, qkv2, out,
        64, 11, 176, HWD, HWD, 1, 0,0, (long)HID*HWD,0, sX,0, ffn_out_b, bufZ, sX,0);
}

// round 10
// speedup vs baseline: 3.1603x; 1.1035x over previous
#include <cuda_runtime.h>
#include <cuda_bf16.h>
#include <math.h>

#define BATCH 4
#define CDIM  64
#define HH    256
#define WW    256
#define HWD   65536          // H*W
#define CHROWS 16384         // C*H
#define HID   170
#define HID2  340

// ---------------- scratch (device globals; no allocations allowed) ----------------
__device__ __nv_bfloat16 g_bufA[(size_t)BATCH * CDIM * HWD];   // ln out / AV out (bf16)
__device__ float         g_bufM[(size_t)BATCH * CDIM * HWD];   // wxw output (fp32)
__device__ float         g_bufZ[(size_t)BATCH * CDIM * HWD];   // hxh output (fp32)
__device__ __nv_bfloat16 g_qkv1[(size_t)BATCH * HID2 * HWD];   // pre-dwconv qkv / ffn hidden
__device__ __nv_bfloat16 g_qkv2[(size_t)BATCH * HID2 * HWD];   // post-dwconv qkv / gated
__device__ float         g_attn[(size_t)BATCH * WW * WW];
__device__ float g_sq[BATCH * HH];
__device__ float g_sk[BATCH * HH];
__device__ float g_wpad[64 * 176];

// ---------------- helpers ----------------
__device__ __forceinline__ void mma8(float* d, unsigned a0, unsigned a1, unsigned a2, unsigned a3,
                                     unsigned b0, unsigned b1) {
    asm volatile(
        "mma.sync.aligned.m16n8k8.row.col.f32.tf32.tf32.f32 "
        "{%0,%1,%2,%3},{%4,%5,%6,%7},{%8,%9},{%0,%1,%2,%3};\n"
        : "+f"(d[0]), "+f"(d[1]), "+f"(d[2]), "+f"(d[3])
        : "r"(a0), "r"(a1), "r"(a2), "r"(a3), "r"(b0), "r"(b1));
}
#define CPA16(dst_u32, src_ptr) \
    asm volatile("cp.async.cg.shared.global [%0], [%1], 16;" :: "r"(dst_u32), "l"(src_ptr))

// ---------------- LayerNorm over channel dim (per pixel), single-read, bf16 out -------
__global__ void ln_kernel(const float* __restrict__ x, const float* __restrict__ w,
                          const float* __restrict__ b, __nv_bfloat16* __restrict__ y)
{
    long p = (long)blockIdx.x * blockDim.x + threadIdx.x;
    if (p >= (long)BATCH * HWD) return;
    int bb  = (int)(p >> 16);
    int pix = (int)(p & (HWD - 1));
    const float* xp = x + (long)bb * CDIM * HWD + pix;
    float v[64];
    float s = 0.f, s2 = 0.f;
#pragma unroll
    for (int c = 0; c < CDIM; c++) {
        float t = xp[(long)c * HWD];
        v[c] = t; s += t; s2 += t * t;
    }
    float mu  = s * (1.0f / CDIM);
    float var = s2 * (1.0f / CDIM) - mu * mu;
    float inv = rsqrtf(var + 1e-5f);
    __nv_bfloat16* yp = y + (long)bb * CDIM * HWD + pix;
#pragma unroll
    for (int c = 0; c < CDIM; c++)
        yp[(long)c * HWD] = __float2bfloat16((v[c] - mu) * inv * w[c] + b[c]);
}

// ---------------- pad ffn_out weight 64x170 -> 64x176 (zero fill) ----------------
__global__ void padw_kernel(const float* __restrict__ w, float* __restrict__ wp)
{
    int i = blockIdx.x * 256 + threadIdx.x;
    if (i >= 64 * 176) return;
    int r = i / 176, c = i - r * 176;
    wp[i] = (c < 170) ? w[r * 170 + c] : 0.f;
}

// ---------------- depthwise 3x3, warp-per-row, shuffle halos, bf16 io ----------------
__global__ void dwconv_rows_kernel(const __nv_bfloat16* __restrict__ x,
                                   const float* __restrict__ wt,
                                   const float* __restrict__ bias,
                                   __nv_bfloat16* __restrict__ y,
                                   int OC, int normCh)
{
    long bidx = blockIdx.x;
    int hb = (int)(bidx & 31) * 8;
    long bc = bidx >> 5;
    int c = (int)(bc % OC);
    int warp = threadIdx.x >> 5, lane = threadIdx.x & 31;
    int h = hb + warp;
    const __nv_bfloat16* xp = x + (bc << 16);
    float b0 = bias[c];
    float acc[8];
#pragma unroll
    for (int j = 0; j < 8; j++) acc[j] = b0;
    const float* wc = wt + c * 9;
#pragma unroll
    for (int kh = -1; kh <= 1; kh++) {
        int hh = h + kh;
        if (hh < 0 || hh >= HH) continue;
        const uint4* rowp = reinterpret_cast<const uint4*>(xp + hh * WW);
        uint4 raw = rowp[lane];
        const __nv_bfloat16* hp = reinterpret_cast<const __nv_bfloat16*>(&raw);
        float vv[8];
#pragma unroll
        for (int j = 0; j < 8; j++) vv[j] = __bfloat162float(hp[j]);
        float vm1 = __shfl_up_sync(0xffffffffu, vv[7], 1);
        if (lane == 0) vm1 = 0.f;
        float vp8 = __shfl_down_sync(0xffffffffu, vv[0], 1);
        if (lane == 31) vp8 = 0.f;
        float vals[10] = {vm1, vv[0], vv[1], vv[2], vv[3], vv[4], vv[5], vv[6], vv[7], vp8};
        const float* wr = wc + (kh + 1) * 3;
#pragma unroll
        for (int kw = 0; kw < 3; kw++) {
            float g = wr[kw];
#pragma unroll
            for (int j = 0; j < 8; j++)
                acc[j] = fmaf(g, vals[j + kw], acc[j]);
        }
    }
    if (c < normCh) {
        float s = 0.f;
#pragma unroll
        for (int j = 0; j < 8; j++) s += acc[j] * acc[j];
#pragma unroll
        for (int o = 16; o > 0; o >>= 1) s += __shfl_xor_sync(0xffffffffu, s, o);
        float inv = 1.f / fmaxf(sqrtf(s), 1e-12f);
#pragma unroll
        for (int j = 0; j < 8; j++) acc[j] *= inv;
    }
    uint4 outr;
    __nv_bfloat16* op = reinterpret_cast<__nv_bfloat16*>(&outr);
#pragma unroll
    for (int j = 0; j < 8; j++) op[j] = __float2bfloat16(acc[j]);
    reinterpret_cast<uint4*>(y + (bc << 16) + h * WW)[lane] = outr;
}

// ---------------- fused FFN depthwise 3x3 + GELU gate, warp-per-row, bf16 io ----------
__global__ void dwconv_gate_kernel(const __nv_bfloat16* __restrict__ x,
                                   const float* __restrict__ wt,
                                   const float* __restrict__ bias,
                                   __nv_bfloat16* __restrict__ g)
{
    long bidx = blockIdx.x;
    int hb = (int)(bidx & 31) * 8;
    long bc = bidx >> 5;            // b*HID + c
    int c = (int)(bc % HID);
    int b = (int)(bc / HID);
    int warp = threadIdx.x >> 5, lane = threadIdx.x & 31;
    int h = hb + warp;
    const __nv_bfloat16* xp1 = x + ((long)b * HID2 + c) * HWD;
    const __nv_bfloat16* xp2 = xp1 + (long)HID * HWD;
    float bb1 = bias[c], bb2 = bias[c + HID];
    float acc1[8], acc2[8];
#pragma unroll
    for (int j = 0; j < 8; j++) { acc1[j] = bb1; acc2[j] = bb2; }
    const float* w1 = wt + c * 9;
    const float* w2 = wt + (c + HID) * 9;
#pragma unroll
    for (int kh = -1; kh <= 1; kh++) {
        int hh = h + kh;
        if (hh < 0 || hh >= HH) continue;
#pragma unroll
        for (int half = 0; half < 2; half++) {
            const __nv_bfloat16* xp = half ? xp2 : xp1;
            float* ac = half ? acc2 : acc1;
            const float* wr0 = (half ? w2 : w1) + (kh + 1) * 3;
            uint4 raw = reinterpret_cast<const uint4*>(xp + hh * WW)[lane];
            const __nv_bfloat16* hp = reinterpret_cast<const __nv_bfloat16*>(&raw);
            float vv[8];
#pragma unroll
            for (int j = 0; j < 8; j++) vv[j] = __bfloat162float(hp[j]);
            float vm1 = __shfl_up_sync(0xffffffffu, vv[7], 1);
            if (lane == 0) vm1 = 0.f;
            float vp8 = __shfl_down_sync(0xffffffffu, vv[0], 1);
            if (lane == 31) vp8 = 0.f;
            float vals[10] = {vm1, vv[0], vv[1], vv[2], vv[3], vv[4], vv[5], vv[6], vv[7], vp8};
#pragma unroll
            for (int kw = 0; kw < 3; kw++) {
                float gg = wr0[kw];
#pragma unroll
                for (int j = 0; j < 8; j++)
                    ac[j] = fmaf(gg, vals[j + kw], ac[j]);
            }
        }
    }
    const float kk = 0.70710678118654752f;
    uint4 outr;
    __nv_bfloat16* op = reinterpret_cast<__nv_bfloat16*>(&outr);
#pragma unroll
    for (int j = 0; j < 8; j++)
        op[j] = __float2bfloat16(0.5f * acc1[j] * (1.0f + erff(acc1[j] * kk)) * acc2[j]);
    reinterpret_cast<uint4*>(g + ((long)b * HID + c) * HWD + h * WW)[lane] = outr;
}

// ---------------- hxh inverse norm: per (b,h) over (c,w), bf16 in ----------------
__global__ void hnorm_kernel(const __nv_bfloat16* __restrict__ src, float* __restrict__ out)
{
    int b = blockIdx.y, h = blockIdx.x;
    int t = threadIdx.x;
    const __nv_bfloat16* p = src + (long)b * (3 * CDIM) * HWD + (long)h * WW + t;
    float s = 0.f;
#pragma unroll
    for (int c = 0; c < CDIM; c++) { float v = __bfloat162float(p[(long)c * HWD]); s += v * v; }
    __shared__ float red[256];
    red[t] = s; __syncthreads();
    for (int o = 128; o > 0; o >>= 1) { if (t < o) red[t] += red[t + o]; __syncthreads(); }
    if (t == 0) out[b * HH + h] = 1.f / fmaxf(sqrtf(red[0]), 1e-12f);
}

// ---------------- softmax over last dim of [B, 256, 256] (fp32) ----------------
__global__ void softmax_kernel(float* __restrict__ attn, const float* __restrict__ temp,
                               const float* __restrict__ sq, const float* __restrict__ sk)
{
    int b = blockIdx.y;
    int r = blockIdx.x;
    float* row = attn + ((long)b * WW + r) * WW;
    int t = threadIdx.x;
    float v = row[t] * temp[0];
    if (sq) v *= sq[b * WW + r] * sk[b * WW + t];
    __shared__ float red[256];
    red[t] = v; __syncthreads();
    for (int o = 128; o > 0; o >>= 1) { if (t < o) red[t] = fmaxf(red[t], red[t + o]); __syncthreads(); }
    float mx = red[0]; __syncthreads();
    float e = __expf(v - mx);
    red[t] = e; __syncthreads();
    for (int o = 128; o > 0; o >>= 1) { if (t < o) red[t] += red[t + o]; __syncthreads(); }
    row[t] = e * (1.f / red[0]);
}

// ---------------- gram kernel, bf16 operands, fp32 atomic out ----------------
// L=0 (wxw): operand addr = k*256 + m        (k-major, m contiguous)
// L=1 (hxh): operand addr = m*256 + (k&255) + (k>>8)*65536
// bf16 smem pitches: P0=136 elems (272 B, 16-mult); P1=24 elems (48 B, 16-mult).
template<int L>
__global__ void __launch_bounds__(256, 2) gram_kernel(
    const __nv_bfloat16* __restrict__ Qb, const __nv_bfloat16* __restrict__ Kb,
    float* __restrict__ Cb, int KS)
{
    constexpr int P0 = 136;
    constexpr int P1 = 24;
    constexpr int SSZ = (L == 0) ? 2 * 16 * P0 : 2 * 128 * P1;
    __shared__ __align__(16) __nv_bfloat16 As[SSZ];
    __shared__ __align__(16) __nv_bfloat16 Bs[SSZ];

    int z = blockIdx.z;
    int b = z / KS, ks = z - b * KS;
    const __nv_bfloat16* Q = Qb + (long)b * (3 * CDIM * HWD);
    const __nv_bfloat16* Kp = Kb + (long)b * (3 * CDIM * HWD);
    float* C = Cb + (long)b * 65536;
    int m0 = blockIdx.x * 128, n0 = blockIdx.y * 128;
    int kchunk = 16384 / KS;
    int kbeg = ks * kchunk, kend = kbeg + kchunk;

    int tid = threadIdx.x, lane = tid & 31, warp = tid >> 5;
    int wm = warp & 1, wn = warp >> 1;
    int r = lane >> 2, c = lane & 3;

    unsigned sA = (unsigned)__cvta_generic_to_shared(As);
    unsigned sB = (unsigned)__cvta_generic_to_shared(Bs);

    auto loadStage = [&](int buf, int k0) {
        if (L == 0) {
            int row = tid >> 4;          // 0..15
            int q   = tid & 15;          // 16 x 16B = 128 bf16
            const __nv_bfloat16* gA = Q  + (long)(k0 + row) * 256 + m0;
            const __nv_bfloat16* gB = Kp + (long)(k0 + row) * 256 + n0;
            unsigned dA = sA + ((buf * 16 + row) * P0) * 2;
            unsigned dB = sB + ((buf * 16 + row) * P0) * 2;
            CPA16(dA + q * 16, gA + q * 8);
            CPA16(dB + q * 16, gB + q * 8);
        } else {
            int m  = tid >> 1;           // 0..127
            int qi = tid & 1;            // 2 x 16B = 16 bf16
            long kb = (long)(k0 >> 8) * 65536 + (k0 & 255);
            const __nv_bfloat16* gA = Q  + (long)(m0 + m) * 256 + kb;
            const __nv_bfloat16* gB = Kp + (long)(n0 + m) * 256 + kb;
            unsigned dA = sA + ((buf * 128 + m) * P1) * 2;
            unsigned dB = sB + ((buf * 128 + m) * P1) * 2;
            CPA16(dA + qi * 16, gA + qi * 8);
            CPA16(dB + qi * 16, gB + qi * 8);
        }
    };

    float acc[16][4];
#pragma unroll
    for (int i = 0; i < 16; i++)
#pragma unroll
        for (int j = 0; j < 4; j++) acc[i][j] = 0.f;

    loadStage(0, kbeg);
    asm volatile("cp.async.commit_group;");
    int buf = 0;

    for (int k0 = kbeg; k0 < kend; k0 += 16) {
        int kn = k0 + 16;
        if (kn < kend) loadStage(buf ^ 1, kn);
        asm volatile("cp.async.commit_group;");
        asm volatile("cp.async.wait_group 1;");
        __syncthreads();

        const __nv_bfloat16* A_ = As + (L == 0 ? buf * 16 * P0 : buf * 128 * P1);
        const __nv_bfloat16* B_ = Bs + (L == 0 ? buf * 16 * P0 : buf * 128 * P1);
#pragma unroll
        for (int ks2 = 0; ks2 < 2; ks2++) {
            int kc = ks2 * 8 + c;
            unsigned a0[4], a1[4], a2[4], a3[4];
#pragma unroll
            for (int mt = 0; mt < 4; mt++) {
                int mr = wm * 64 + mt * 16 + r;
                if (L == 0) {
                    a0[mt] = __float_as_uint(__bfloat162float(A_[kc * P0 + mr]));
                    a1[mt] = __float_as_uint(__bfloat162float(A_[kc * P0 + mr + 8]));
                    a2[mt] = __float_as_uint(__bfloat162float(A_[(kc + 4) * P0 + mr]));
                    a3[mt] = __float_as_uint(__bfloat162float(A_[(kc + 4) * P0 + mr + 8]));
                } else {
                    a0[mt] = __float_as_uint(__bfloat162float(A_[mr * P1 + kc]));
                    a1[mt] = __float_as_uint(__bfloat162float(A_[(mr + 8) * P1 + kc]));
                    a2[mt] = __float_as_uint(__bfloat162float(A_[mr * P1 + kc + 4]));
                    a3[mt] = __float_as_uint(__bfloat162float(A_[(mr + 8) * P1 + kc + 4]));
                }
            }
#pragma unroll
            for (int j = 0; j < 4; j++) {
                int nn = wn * 32 + j * 8 + r;
                unsigned b0, b1;
                if (L == 0) {
                    b0 = __float_as_uint(__bfloat162float(B_[kc * P0 + nn]));
                    b1 = __float_as_uint(__bfloat162float(B_[(kc + 4) * P0 + nn]));
                } else {
                    b0 = __float_as_uint(__bfloat162float(B_[nn * P1 + kc]));
                    b1 = __float_as_uint(__bfloat162float(B_[nn * P1 + kc + 4]));
                }
#pragma unroll
                for (int mt = 0; mt < 4; mt++)
                    mma8(acc[mt * 4 + j], a0[mt], a1[mt], a2[mt], a3[mt], b0, b1);
            }
        }
        __syncthreads();
        buf ^= 1;
    }

#pragma unroll
    for (int mt = 0; mt < 4; mt++) {
#pragma unroll
        for (int j = 0; j < 4; j++) {
            int mrow = m0 + wm * 64 + mt * 16 + r;
            int n    = n0 + wn * 32 + j * 8 + c * 2;
            float* ci = acc[mt * 4 + j];
            atomicAdd(&C[(long)mrow * 256 + n],           ci[0]);
            atomicAdd(&C[(long)mrow * 256 + n + 1],       ci[1]);
            atomicAdd(&C[(long)(mrow + 8) * 256 + n],     ci[2]);
            atomicAdd(&C[(long)(mrow + 8) * 256 + n + 1], ci[3]);
        }
    }
}

// ---------------- unified cp.async tf32 GEMM, mixed fp32/bf16 operands ----------------
// C[m,n] = sum_k A[m*lda + k] * B[k*sbk + n]  (+bias[m], +res)
// ABF/BBF/CBF: 1 = bf16 storage for A / B / C. Compute stays tf32 MMA, fp32 accum.
// Smem pitches chosen so pitch*elemsize is a multiple of 16 B for cp.async:
//   A: fp32 pitch 20 (80 B) / bf16 pitch 24 (48 B)
//   B: fp32 pitch 68 (272 B) / bf16 pitch 72 (144 B)
template<int MT, int ABF, int BBF, int CBF>
__global__ void __launch_bounds__(128, (MT == 1) ? 4 : 3) mma2_kernel(
    const void* __restrict__ Av, const void* __restrict__ Bv, void* __restrict__ Cv,
    int M, int kit16, int lda, long sbk, int ldc, int zdiv,
    long sA1, long sA2, long sB1, long sB2, long sC1, long sC2,
    const float* __restrict__ bias,
    const float* __restrict__ res, long sR1, long sR2)
{
    constexpr int BM = MT * 64;
    constexpr int PA = ABF ? 24 : 20;
    constexpr int PB = BBF ? 72 : 68;
    constexpr int esA = ABF ? 2 : 4;
    constexpr int esB = BBF ? 2 : 4;
    constexpr int esC = CBF ? 2 : 4;
    constexpr int EA = ABF ? 8 : 4;          // elems per 16B chunk
    constexpr int EB = BBF ? 8 : 4;
    constexpr int cprA = 16 / EA;            // chunks per A row (16 k elems)
    constexpr int cprB = 64 / EB;            // chunks per B row (64 n elems)
    __shared__ __align__(16) char AsRaw[2 * BM * PA * esA];
    __shared__ __align__(16) char BsRaw[2 * 16 * PB * esB];

    int z = blockIdx.z;
    int z1 = z / zdiv, z2 = z - z1 * zdiv;
    const char* Apc = (const char*)Av + ((long)z1 * sA1 + (long)z2 * sA2) * esA;
    const char* Bpc = (const char*)Bv + ((long)z1 * sB1 + (long)z2 * sB2) * esB;
    char*       Cpc = (char*)Cv + ((long)z1 * sC1 + (long)z2 * sC2) * esC;

    int m0 = blockIdx.x * BM;
    int n0 = blockIdx.y * 64;

    int tid = threadIdx.x, lane = tid & 31, warp = tid >> 5;
    int r = lane >> 2, c = lane & 3;

    unsigned sAu = (unsigned)__cvta_generic_to_shared(AsRaw);
    unsigned sBu = (unsigned)__cvta_generic_to_shared(BsRaw);

    auto loadStage = [&](int buf, int kit) {
        int k0 = kit * 16;
        // A: BM rows x 16 k
#pragma unroll
        for (int i = 0; i < BM * cprA / 128; i++) {
            int q = tid + i * 128;
            int m = q / cprA, sub = q - m * cprA;
            int gm = min(m0 + m, M - 1);
            CPA16(sAu + ((buf * BM + m) * PA + sub * EA) * esA,
                  Apc + ((long)gm * lda + k0 + sub * EA) * esA);
        }
        // B: 16 k rows x 64 n
#pragma unroll
        for (int i = 0; i < 16 * cprB / 128; i++) {
            int q = tid + i * 128;
            int k = q / cprB, sub = q - k * cprB;
            CPA16(sBu + ((buf * 16 + k) * PB + sub * EB) * esB,
                  Bpc + ((long)(k0 + k) * sbk + n0 + sub * EB) * esB);
        }
    };

    float acc[MT * 8][4];
#pragma unroll
    for (int i = 0; i < MT * 8; i++)
#pragma unroll
        for (int j = 0; j < 4; j++) acc[i][j] = 0.f;

    loadStage(0, 0);
    asm volatile("cp.async.commit_group;");
    int buf = 0;

    for (int kit = 0; kit < kit16; kit++) {
        if (kit + 1 < kit16) loadStage(buf ^ 1, kit + 1);
        asm volatile("cp.async.commit_group;");
        asm volatile("cp.async.wait_group 1;");
        __syncthreads();

        const char* A_ = AsRaw + buf * BM * PA * esA;
        const char* B_ = BsRaw + buf * 16 * PB * esB;
        auto ldA = [&](int idx) -> unsigned {
            if (ABF) return __float_as_uint(__bfloat162float(((const __nv_bfloat16*)A_)[idx]));
            return __float_as_uint(((const float*)A_)[idx]);
        };
        auto ldB = [&](int idx) -> unsigned {
            if (BBF) return __float_as_uint(__bfloat162float(((const __nv_bfloat16*)B_)[idx]));
            return __float_as_uint(((const float*)B_)[idx]);
        };
#pragma unroll
        for (int ks2 = 0; ks2 < 2; ks2++) {
            int kc = ks2 * 8 + c;
            unsigned a0[MT], a1[MT], a2[MT], a3[MT];
#pragma unroll
            for (int mt = 0; mt < MT; mt++) {
                int mr = warp * (MT * 16) + mt * 16 + r;
                a0[mt] = ldA(mr * PA + kc);
                a1[mt] = ldA((mr + 8) * PA + kc);
                a2[mt] = ldA(mr * PA + kc + 4);
                a3[mt] = ldA((mr + 8) * PA + kc + 4);
            }
#pragma unroll
            for (int j = 0; j < 8; j++) {
                int nn = j * 8 + r;
                unsigned b0 = ldB(kc * PB + nn);
                unsigned b1 = ldB((kc + 4) * PB + nn);
#pragma unroll
                for (int mt = 0; mt < MT; mt++)
                    mma8(acc[mt * 8 + j], a0[mt], a1[mt], a2[mt], a3[mt], b0, b1);
            }
        }
        __syncthreads();
        buf ^= 1;
    }

    const float* Rp = res ? res + (long)z1 * sR1 + (long)z2 * sR2 : nullptr;
#pragma unroll
    for (int mt = 0; mt < MT; mt++) {
#pragma unroll
        for (int j = 0; j < 8; j++) {
            int mA = m0 + warp * (MT * 16) + mt * 16 + r;
            int n  = n0 + j * 8 + c * 2;
            float* ci = acc[mt * 8 + j];
#pragma unroll
            for (int half = 0; half < 2; half++) {
                int mrow = mA + half * 8;
                if (mrow >= M) continue;
                float bv = bias ? bias[mrow] : 0.f;
                float v0 = ci[half * 2 + 0] + bv;
                float v1 = ci[half * 2 + 1] + bv;
                long off = (long)mrow * ldc + n;
                if (Rp) { v0 += Rp[off]; v1 += Rp[off + 1]; }
                if (CBF) {
                    __nv_bfloat162 h = __floats2bfloat162_rn(v0, v1);
                    *reinterpret_cast<__nv_bfloat162*>(Cpc + off * 2) = h;
                } else {
                    *reinterpret_cast<float2*>(Cpc + off * 4) = make_float2(v0, v1);
                }
            }
        }
    }
}

extern "C" void kernel_launch(void* const* d_in, const int* in_sizes, int n_in,
                              void* d_out, int out_size)
{
    const float* x        = (const float*)d_in[0];
    const float* w_ln_w   = (const float*)d_in[2];
    const float* w_ln_b   = (const float*)d_in[3];
    const float* w_qkv_w  = (const float*)d_in[4];
    const float* w_qkv_b  = (const float*)d_in[5];
    const float* w_dw_w   = (const float*)d_in[6];
    const float* w_dw_b   = (const float*)d_in[7];
    const float* w_proj_w = (const float*)d_in[8];
    const float* w_proj_b = (const float*)d_in[9];
    const float* w_temp   = (const float*)d_in[10];
    const float* h_ln_w   = (const float*)d_in[11];
    const float* h_ln_b   = (const float*)d_in[12];
    const float* h_qkv_w  = (const float*)d_in[13];
    const float* h_qkv_b  = (const float*)d_in[14];
    const float* h_dw_w   = (const float*)d_in[15];
    const float* h_dw_b   = (const float*)d_in[16];
    const float* h_proj_w = (const float*)d_in[17];
    const float* h_proj_b = (const float*)d_in[18];
    const float* h_temp   = (const float*)d_in[19];
    const float* n2_w     = (const float*)d_in[20];
    const float* n2_b     = (const float*)d_in[21];
    const float* ffn_in_w = (const float*)d_in[22];
    const float* ffn_in_b = (const float*)d_in[23];
    const float* ffn_dw_w = (const float*)d_in[24];
    const float* ffn_dw_b = (const float*)d_in[25];
    const float* ffn_out_w= (const float*)d_in[26];
    const float* ffn_out_b= (const float*)d_in[27];
    float* out = (float*)d_out;

    __nv_bfloat16 *bufA, *qkv1, *qkv2;
    float *bufM, *bufZ, *attn, *sq, *sk, *wpad;
    cudaGetSymbolAddress((void**)&bufA, g_bufA);
    cudaGetSymbolAddress((void**)&bufM, g_bufM);
    cudaGetSymbolAddress((void**)&bufZ, g_bufZ);
    cudaGetSymbolAddress((void**)&qkv1, g_qkv1);
    cudaGetSymbolAddress((void**)&qkv2, g_qkv2);
    cudaGetSymbolAddress((void**)&attn, g_attn);
    cudaGetSymbolAddress((void**)&sq,   g_sq);
    cudaGetSymbolAddress((void**)&sk,   g_sk);
    cudaGetSymbolAddress((void**)&wpad, g_wpad);

    const long sX = (long)CDIM * HWD;
    const long sQ = (long)3 * CDIM * HWD;
    const int KS = 32;

    padw_kernel<<<(64 * 176 + 255) / 256, 256>>>(ffn_out_w, wpad);

    // ================= attention (WxW) =================
    ln_kernel<<<(BATCH * HWD) / 256, 256>>>(x, w_ln_w, w_ln_b, bufA);
    // qkv: A=W fp32, B=ln bf16, C=qkv1 bf16
    mma2_kernel<1,0,1,1><<<dim3(3, 1024, BATCH), 128>>>(w_qkv_w, bufA, qkv1,
        192, 4, 64, HWD, HWD, 1, 0,0, sX,0, sQ,0, w_qkv_b, nullptr, 0,0);
    dwconv_rows_kernel<<<BATCH*192*32, 256>>>(qkv1, w_dw_w, w_dw_b, qkv2, 192, 128);
    cudaMemsetAsync(attn, 0, (size_t)BATCH * WW * WW * sizeof(float));
    gram_kernel<0><<<dim3(2, 2, BATCH * KS), 256>>>(qkv2, qkv2 + 64*(long)HWD, attn, KS);
    softmax_kernel<<<dim3(WW, BATCH), 256>>>(attn, w_temp, nullptr, nullptr);
    // AV: A=v bf16, B=attn fp32, C=bufA bf16
    mma2_kernel<2,1,0,1><<<dim3(128, 4, BATCH), 128>>>(qkv2 + 128*(long)HWD, attn, bufA,
        CHROWS, 16, 256, 256, 256, 1, sQ,0, (long)WW*WW,0, sX,0, nullptr, nullptr, 0,0);
    // proj + residual x -> bufM (fp32)
    mma2_kernel<1,0,1,0><<<dim3(1, 1024, BATCH), 128>>>(w_proj_w, bufA, bufM,
        64, 4, 64, HWD, HWD, 1, 0,0, sX,0, sX,0, w_proj_b, x, sX,0);

    // ================= attention (HxH) =================
    ln_kernel<<<(BATCH * HWD) / 256, 256>>>(bufM, h_ln_w, h_ln_b, bufA);
    mma2_kernel<1,0,1,1><<<dim3(3, 1024, BATCH), 128>>>(h_qkv_w, bufA, qkv1,
        192, 4, 64, HWD, HWD, 1, 0,0, sX,0, sQ,0, h_qkv_b, nullptr, 0,0);
    dwconv_rows_kernel<<<BATCH*192*32, 256>>>(qkv1, h_dw_w, h_dw_b, qkv2, 192, 0);
    hnorm_kernel<<<dim3(HH, BATCH), 256>>>(qkv2,                sq);
    hnorm_kernel<<<dim3(HH, BATCH), 256>>>(qkv2 + 64*(long)HWD, sk);
    cudaMemsetAsync(attn, 0, (size_t)BATCH * WW * WW * sizeof(float));
    gram_kernel<1><<<dim3(2, 2, BATCH * KS), 256>>>(qkv2, qkv2 + 64*(long)HWD, attn, KS);
    softmax_kernel<<<dim3(WW, BATCH), 256>>>(attn, h_temp, sq, sk);
    // AV: A=attn fp32, B=v bf16, C=bufA bf16
    mma2_kernel<2,0,1,1><<<dim3(2, 4, BATCH * 64), 128>>>(attn, qkv2 + 128*(long)HWD, bufA,
        256, 16, 256, 256, 256, 64, (long)WW*WW,0, sQ,(long)HWD, sX,(long)HWD,
        nullptr, nullptr, 0,0);
    // proj + residual m -> bufZ (fp32)
    mma2_kernel<1,0,1,0><<<dim3(1, 1024, BATCH), 128>>>(h_proj_w, bufA, bufZ,
        64, 4, 64, HWD, HWD, 1, 0,0, sX,0, sX,0, h_proj_b, bufM, sX,0);

    // ================= FFN =================
    ln_kernel<<<(BATCH * HWD) / 256, 256>>>(bufZ, n2_w, n2_b, bufA);
    mma2_kernel<2,0,1,1><<<dim3(3, 1024, BATCH), 128>>>(ffn_in_w, bufA, qkv1,
        HID2, 4, 64, HWD, HWD, 1, 0,0, sX,0, (long)HID2*HWD,0, ffn_in_b, nullptr, 0,0);
    dwconv_gate_kernel<<<BATCH*HID*32, 256>>>(qkv1, ffn_dw_w, ffn_dw_b, qkv2);
    // out = Wout(padded) @ gated(bf16) + bias + z (fp32 out)
    mma2_kernel<1,0,1,0><<<dim3(1, 1024, BATCH), 128>>>(wpad, qkv2, out,
        64, 11, 176, HWD, HWD, 1, 0,0, (long)HID*HWD,0, sX,0, ffn_out_b, bufZ, sX,0);
}